// round 4
// baseline (speedup 1.0000x reference)
#include <cuda_runtime.h>
#include <math.h>

// ---------------- scratch (device globals; no allocation allowed) ----------------
__device__ float g_H1[16384 * 512];   // lufeat@W1+b1
__device__ float g_H [16384 * 256];   // (..)@W2+b2, then normalized in place
__device__ float g_MB[40 * 256];      // memory bank after scan
__device__ float g_UF[8192 * 296];    // concat(ufeat, um)
__device__ float g_Y3[8192 * 256];    // layer-3 pre/post activation (in place)
__device__ float g_Y4[8192 * 64];     // layer-4 pre/post activation (in place)
__device__ float g_PS[64 * 256];      // BN partial sums
__device__ float g_PQ[64 * 256];      // BN partial sumsq
__device__ float g_MEAN[256];
__device__ float g_INV[256];

// ---------------- generic tiled SGEMM with bias: C = A(MxK) @ B(KxN) + bias ----------------
// Requirements: M % 128 == 0, K % 8 == 0, N % 4 == 0 (guards on N only).
__global__ __launch_bounds__(256) void sgemm_bias_kernel(
    const float* __restrict__ A, const float* __restrict__ B,
    const float* __restrict__ bias, float* __restrict__ C,
    int M, int N, int K)
{
    const int BM = 128, BN = 128, BK = 8, TM = 8, TN = 8;
    __shared__ float As[BK][BM];
    __shared__ float Bs[BK][BN];

    int tid = threadIdx.x;
    int bm = blockIdx.y * BM;
    int bn = blockIdx.x * BN;
    int tx = tid & 15;        // 0..15 -> column group
    int ty = tid >> 4;        // 0..15 -> row group
    int aRow = tid >> 1, aCol = (tid & 1) << 2;   // 128x8 A tile, float4 each
    int bRow = tid >> 5, bCol = (tid & 31) << 2;  // 8x128 B tile, float4 each

    float acc[TM][TN];
#pragma unroll
    for (int i = 0; i < TM; i++)
#pragma unroll
        for (int j = 0; j < TN; j++) acc[i][j] = 0.f;

    const float* Aptr = A + (size_t)(bm + aRow) * K + aCol;

    for (int k0 = 0; k0 < K; k0 += BK) {
        float4 av = *(const float4*)(Aptr + k0);
        As[aCol + 0][aRow] = av.x;
        As[aCol + 1][aRow] = av.y;
        As[aCol + 2][aRow] = av.z;
        As[aCol + 3][aRow] = av.w;

        float4 bv = make_float4(0.f, 0.f, 0.f, 0.f);
        if (bn + bCol < N)
            bv = *(const float4*)(B + (size_t)(k0 + bRow) * N + bn + bCol);
        *(float4*)&Bs[bRow][bCol] = bv;
        __syncthreads();

#pragma unroll
        for (int k = 0; k < BK; k++) {
            float ra[TM], rb[TN];
            *(float4*)&ra[0] = *(const float4*)&As[k][ty * TM];
            *(float4*)&ra[4] = *(const float4*)&As[k][ty * TM + 4];
            *(float4*)&rb[0] = *(const float4*)&Bs[k][tx * TN];
            *(float4*)&rb[4] = *(const float4*)&Bs[k][tx * TN + 4];
#pragma unroll
            for (int i = 0; i < TM; i++)
#pragma unroll
                for (int j = 0; j < TN; j++)
                    acc[i][j] = fmaf(ra[i], rb[j], acc[i][j]);
        }
        __syncthreads();
    }

#pragma unroll
    for (int i = 0; i < TM; i++) {
        int row = bm + ty * TM + i;
#pragma unroll
        for (int j = 0; j < TN; j += 4) {
            int col = bn + tx * TN + j;
            if (col < N) {
                float4 v;
                v.x = acc[i][j + 0] + bias[col + 0];
                v.y = acc[i][j + 1] + bias[col + 1];
                v.z = acc[i][j + 2] + bias[col + 2];
                v.w = acc[i][j + 3] + bias[col + 3];
                *(float4*)(C + (size_t)row * N + col) = v;
            }
        }
    }
}

// ---------------- row L2-normalize H (16384 x 256), one warp per row ----------------
__global__ void norm_rows_kernel(float* __restrict__ H)
{
    int warp = (blockIdx.x * blockDim.x + threadIdx.x) >> 5;
    int lane = threadIdx.x & 31;
    if (warp >= 16384) return;
    float* rowp = H + (size_t)warp * 256;
    float4 a = *(const float4*)(rowp + lane * 4);
    float4 b = *(const float4*)(rowp + 128 + lane * 4);
    float s = a.x * a.x + a.y * a.y + a.z * a.z + a.w * a.w
            + b.x * b.x + b.y * b.y + b.z * b.z + b.w * b.w;
#pragma unroll
    for (int o = 16; o; o >>= 1) s += __shfl_xor_sync(0xffffffffu, s, o);
    float inv = 1.0f / sqrtf(s);
    a.x *= inv; a.y *= inv; a.z *= inv; a.w *= inv;
    b.x *= inv; b.y *= inv; b.z *= inv; b.w *= inv;
    *(float4*)(rowp + lane * 4) = a;
    *(float4*)(rowp + 128 + lane * 4) = b;
}

// ---------------- memory-bank EMA scan: one block per class, thread = dim ----------------
__global__ void scan_kernel(const float* __restrict__ H, const int* __restrict__ llabel,
                            const float* __restrict__ mbank0, const float* __restrict__ start0,
                            float* __restrict__ MB, float* __restrict__ out_mbank)
{
    int c = blockIdx.x;       // 0..39
    int d = threadIdx.x;      // 0..255
    __shared__ int labs[256];
    float row = mbank0[c * 256 + d];
    bool started = (start0[c] != 0.0f);
    for (int i0 = 0; i0 < 8192; i0 += 256) {
        __syncthreads();
        labs[d] = llabel[i0 + d];
        __syncthreads();
        for (int j = 0; j < 256; j++) {
            if (labs[j] == c) {
                float f = H[(size_t)(i0 + j) * 256 + d];
                row = started ? fmaf(0.9f, row, 0.1f * f) : f;
                started = true;
            }
        }
    }
    MB[c * 256 + d] = row;
    out_mbank[c * 256 + d] = row;
}

// ---------------- distances: lscores for labeled, UF = [ufeat | um] for unlabeled ----------------
__global__ void dist_kernel(const float* __restrict__ H, const float* __restrict__ MB,
                            float* __restrict__ lscores, float* __restrict__ UF)
{
    __shared__ float mb[40 * 256];
    for (int i = threadIdx.x; i < 40 * 256; i += blockDim.x) mb[i] = MB[i];
    __syncthreads();

    int nwarp = (gridDim.x * blockDim.x) >> 5;
    int warp = (blockIdx.x * blockDim.x + threadIdx.x) >> 5;
    int lane = threadIdx.x & 31;

    for (int row = warp; row < 16384; row += nwarp) {
        float h[8];
#pragma unroll
        for (int k = 0; k < 8; k++) h[k] = H[(size_t)row * 256 + lane + 32 * k];
        if (row < 8192) {
            float best = 3.4e38f;
            for (int c = 0; c < 40; c++) {
                float s = 0.f;
#pragma unroll
                for (int k = 0; k < 8; k++) {
                    float dl = h[k] - mb[c * 256 + lane + 32 * k];
                    s = fmaf(dl, dl, s);
                }
#pragma unroll
                for (int o = 16; o; o >>= 1) s += __shfl_xor_sync(0xffffffffu, s, o);
                best = fminf(best, s);
            }
            if (lane == 0) lscores[row] = sqrtf(best);
        } else {
            int r = row - 8192;
#pragma unroll
            for (int k = 0; k < 8; k++)
                UF[(size_t)r * 296 + lane + 32 * k] = h[k];
            for (int c = 0; c < 40; c++) {
                float s = 0.f;
#pragma unroll
                for (int k = 0; k < 8; k++) {
                    float dl = h[k] - mb[c * 256 + lane + 32 * k];
                    s = fmaf(dl, dl, s);
                }
#pragma unroll
                for (int o = 16; o; o >>= 1) s += __shfl_xor_sync(0xffffffffu, s, o);
                if (lane == 0) UF[(size_t)r * 296 + 256 + c] = sqrtf(s);
            }
        }
    }
}

// ---------------- BN stage 1: per-block partial column sums (deterministic) ----------------
__global__ void bn_part_kernel(const float* __restrict__ X, int cols,
                               float* __restrict__ ps, float* __restrict__ pq)
{
    int col = threadIdx.x;          // blockDim.x == cols
    int r0 = blockIdx.x * 128;
    float s = 0.f, q = 0.f;
    for (int r = r0; r < r0 + 128; r++) {
        float v = X[(size_t)r * cols + col];
        s += v;
        q = fmaf(v, v, q);
    }
    ps[blockIdx.x * cols + col] = s;
    pq[blockIdx.x * cols + col] = q;
}

// ---------------- BN stage 2: fold 64 partials -> mean, 1/sqrt(var+eps) ----------------
__global__ void bn_stats_kernel(const float* __restrict__ ps, const float* __restrict__ pq,
                                int cols, float* __restrict__ mean, float* __restrict__ inv)
{
    int col = threadIdx.x;
    float s = 0.f, q = 0.f;
    for (int b = 0; b < 64; b++) { s += ps[b * cols + col]; q += pq[b * cols + col]; }
    float mu = s * (1.0f / 8192.0f);
    float var = q * (1.0f / 8192.0f) - mu * mu;
    mean[col] = mu;
    inv[col] = 1.0f / sqrtf(var + 1e-5f);
}

// ---------------- BN apply + ReLU (in place); cols is a power of two ----------------
__global__ void bn_apply_kernel(float* __restrict__ X, int n, int cols,
                                const float* __restrict__ mean, const float* __restrict__ inv,
                                const float* __restrict__ g, const float* __restrict__ be)
{
    int idx = blockIdx.x * blockDim.x + threadIdx.x;
    if (idx < n) {
        int col = idx & (cols - 1);
        float v = (X[idx] - mean[col]) * inv[col] * g[col] + be[col];
        X[idx] = fmaxf(v, 0.f);
    }
}

// ---------------- final matvec: uscores = U4(8192x64) @ W5(64) + b5 ----------------
__global__ void gemm5_kernel(const float* __restrict__ U4, const float* __restrict__ W5,
                             const float* __restrict__ b5, float* __restrict__ out)
{
    int warp = (blockIdx.x * blockDim.x + threadIdx.x) >> 5;
    int lane = threadIdx.x & 31;
    if (warp >= 8192) return;
    float s = U4[(size_t)warp * 64 + lane] * W5[lane]
            + U4[(size_t)warp * 64 + 32 + lane] * W5[32 + lane];
#pragma unroll
    for (int o = 16; o; o >>= 1) s += __shfl_xor_sync(0xffffffffu, s, o);
    if (lane == 0) out[warp] = s + b5[0];
}

// ---------------- launcher ----------------
extern "C" void kernel_launch(void* const* d_in, const int* in_sizes, int n_in,
                              void* d_out, int out_size)
{
    const float* lufeat = (const float*)d_in[0];
    const int*   llabel = (const int*)  d_in[1];
    const float* W1 = (const float*)d_in[2];
    const float* b1 = (const float*)d_in[3];
    const float* W2 = (const float*)d_in[4];
    const float* b2 = (const float*)d_in[5];
    const float* W3 = (const float*)d_in[6];
    const float* b3 = (const float*)d_in[7];
    const float* W4 = (const float*)d_in[8];
    const float* b4 = (const float*)d_in[9];
    const float* W5 = (const float*)d_in[10];
    const float* b5 = (const float*)d_in[11];
    const float* g1 = (const float*)d_in[12];
    const float* be1 = (const float*)d_in[13];
    const float* g2 = (const float*)d_in[14];
    const float* be2 = (const float*)d_in[15];
    const float* mbank0 = (const float*)d_in[16];
    const float* start0 = (const float*)d_in[17];
    float* out = (float*)d_out;

    float *H1, *H, *MB, *UF, *Y3, *Y4, *PS, *PQ, *MEAN, *INV;
    cudaGetSymbolAddress((void**)&H1, g_H1);
    cudaGetSymbolAddress((void**)&H,  g_H);
    cudaGetSymbolAddress((void**)&MB, g_MB);
    cudaGetSymbolAddress((void**)&UF, g_UF);
    cudaGetSymbolAddress((void**)&Y3, g_Y3);
    cudaGetSymbolAddress((void**)&Y4, g_Y4);
    cudaGetSymbolAddress((void**)&PS, g_PS);
    cudaGetSymbolAddress((void**)&PQ, g_PQ);
    cudaGetSymbolAddress((void**)&MEAN, g_MEAN);
    cudaGetSymbolAddress((void**)&INV,  g_INV);

    // h = (lufeat @ W1 + b1) @ W2 + b2 ; normalize rows
    sgemm_bias_kernel<<<dim3(4, 128), 256>>>(lufeat, W1, b1, H1, 16384, 512, 1024);
    sgemm_bias_kernel<<<dim3(2, 128), 256>>>(H1, W2, b2, H, 16384, 256, 512);
    norm_rows_kernel<<<2048, 256>>>(H);

    // memory bank scan (writes both scratch MB and output mbank region)
    scan_kernel<<<40, 256>>>(H, llabel, mbank0, start0, MB, out + 16384);

    // distances: lscores to d_out[0..8191], UF = [ufeat | um]
    dist_kernel<<<128, 256>>>(H, MB, out, UF);

    // layer 3: UF(8192x296) @ W3(296x256) + b3 -> BN -> ReLU
    sgemm_bias_kernel<<<dim3(2, 64), 256>>>(UF, W3, b3, Y3, 8192, 256, 296);
    bn_part_kernel<<<64, 256>>>(Y3, 256, PS, PQ);
    bn_stats_kernel<<<1, 256>>>(PS, PQ, 256, MEAN, INV);
    bn_apply_kernel<<<(8192 * 256 + 255) / 256, 256>>>(Y3, 8192 * 256, 256, MEAN, INV, g1, be1);

    // layer 4: Y3(8192x256) @ W4(256x64) + b4 -> BN -> ReLU
    sgemm_bias_kernel<<<dim3(1, 64), 256>>>(Y3, W4, b4, Y4, 8192, 64, 256);
    bn_part_kernel<<<64, 64>>>(Y4, 64, PS, PQ);
    bn_stats_kernel<<<1, 64>>>(PS, PQ, 64, MEAN, INV);
    bn_apply_kernel<<<(8192 * 64 + 255) / 256, 256>>>(Y4, 8192 * 64, 64, MEAN, INV, g2, be2);

    // uscores
    gemm5_kernel<<<1024, 256>>>(Y4, W5, b5, out + 8192);
}

// round 6
// speedup vs baseline: 1.8089x; 1.8089x over previous
#include <cuda_runtime.h>
#include <math.h>

// ---------------- scratch (device globals; no allocation allowed) ----------------
__device__ float g_H1[16384 * 512];   // lufeat@W1+b1
__device__ float g_H [16384 * 256];   // (..)@W2+b2, then normalized in place
__device__ float g_MB[40 * 256];      // memory bank after scan
__device__ float g_UF[8192 * 304];    // concat(ufeat, um), padded 296->304
__device__ float g_Y3[8192 * 256];    // layer-3 pre/post activation (in place)
__device__ float g_Y4[8192 * 64];     // layer-4 pre/post activation (in place)
__device__ float g_PS[64 * 256];      // BN partial sums
__device__ float g_PQ[64 * 256];      // BN partial sumsq
__device__ float g_MEAN[256];
__device__ float g_INV[256];
__device__ int   g_OCC[40 * 8192];    // per-class ordered occurrence indices
__device__ int   g_CNT[40];           // per-class occurrence counts

// ---------------- double-buffered tiled SGEMM with bias: C = A(MxK) @ B(KxN) + bias ----
// M % 128 == 0. A row stride = lda (>= K, pad columns must be zero). B row stride = N.
__global__ __launch_bounds__(256, 2) void sgemm_bias_db(
    const float* __restrict__ A, int lda,
    const float* __restrict__ B, const float* __restrict__ bias,
    float* __restrict__ C, int M, int N, int K)
{
    const int BM = 128, BN = 128, BK = 16, TM = 8, TN = 8;
    __shared__ float As[2][BK][BM];
    __shared__ float Bs[2][BK][BN];

    int tid = threadIdx.x;
    int bm = blockIdx.y * BM;
    int bn = blockIdx.x * BN;
    int tx = tid & 15;         // column group
    int ty = tid >> 4;         // row group
    int aRow = tid >> 1, aCol = (tid & 1) * 8;     // A: 128 x 16, 8 floats/thread
    int bRow = tid >> 4, bCol = (tid & 15) * 8;    // B: 16 x 128, 8 floats/thread
    bool bvalid = (bn + bCol < N);

    const float* Abase = A + (size_t)(bm + aRow) * lda + aCol;
    const float* Bbase = B + bn + bCol;

    float acc[TM][TN];
#pragma unroll
    for (int i = 0; i < TM; i++)
#pragma unroll
        for (int j = 0; j < TN; j++) acc[i][j] = 0.f;

    int nk = (K + BK - 1) / BK;

    float4 a0, a1, b0, b1;
    // prefetch tile 0
    a0 = *(const float4*)(Abase);
    a1 = *(const float4*)(Abase + 4);
    {
        float4 z = make_float4(0.f, 0.f, 0.f, 0.f);
        b0 = z; b1 = z;
        if (bvalid && bRow < K) {
            const float* p = Bbase + (size_t)bRow * N;
            b0 = *(const float4*)p; b1 = *(const float4*)(p + 4);
        }
    }
    // store stage 0
    As[0][aCol + 0][aRow] = a0.x; As[0][aCol + 1][aRow] = a0.y;
    As[0][aCol + 2][aRow] = a0.z; As[0][aCol + 3][aRow] = a0.w;
    As[0][aCol + 4][aRow] = a1.x; As[0][aCol + 5][aRow] = a1.y;
    As[0][aCol + 6][aRow] = a1.z; As[0][aCol + 7][aRow] = a1.w;
    *(float4*)&Bs[0][bRow][bCol]     = b0;
    *(float4*)&Bs[0][bRow][bCol + 4] = b1;
    __syncthreads();

    for (int t = 0; t < nk; t++) {
        int cur = t & 1;
        bool more = (t + 1 < nk);
        if (more) {
            int k0 = (t + 1) * BK;
            a0 = *(const float4*)(Abase + k0);
            a1 = *(const float4*)(Abase + k0 + 4);
            float4 z = make_float4(0.f, 0.f, 0.f, 0.f);
            b0 = z; b1 = z;
            if (bvalid && k0 + bRow < K) {
                const float* p = Bbase + (size_t)(k0 + bRow) * N;
                b0 = *(const float4*)p; b1 = *(const float4*)(p + 4);
            }
        }
#pragma unroll
        for (int k = 0; k < BK; k++) {
            float ra[TM], rb[TN];
            *(float4*)&ra[0] = *(const float4*)&As[cur][k][ty * TM];
            *(float4*)&ra[4] = *(const float4*)&As[cur][k][ty * TM + 4];
            *(float4*)&rb[0] = *(const float4*)&Bs[cur][k][tx * TN];
            *(float4*)&rb[4] = *(const float4*)&Bs[cur][k][tx * TN + 4];
#pragma unroll
            for (int i = 0; i < TM; i++)
#pragma unroll
                for (int j = 0; j < TN; j++)
                    acc[i][j] = fmaf(ra[i], rb[j], acc[i][j]);
        }
        if (more) {
            int nxt = cur ^ 1;
            As[nxt][aCol + 0][aRow] = a0.x; As[nxt][aCol + 1][aRow] = a0.y;
            As[nxt][aCol + 2][aRow] = a0.z; As[nxt][aCol + 3][aRow] = a0.w;
            As[nxt][aCol + 4][aRow] = a1.x; As[nxt][aCol + 5][aRow] = a1.y;
            As[nxt][aCol + 6][aRow] = a1.z; As[nxt][aCol + 7][aRow] = a1.w;
            *(float4*)&Bs[nxt][bRow][bCol]     = b0;
            *(float4*)&Bs[nxt][bRow][bCol + 4] = b1;
        }
        __syncthreads();
    }

#pragma unroll
    for (int i = 0; i < TM; i++) {
        int row = bm + ty * TM + i;
#pragma unroll
        for (int j = 0; j < TN; j += 4) {
            int col = bn + tx * TN + j;
            if (col < N) {
                float4 v;
                v.x = acc[i][j + 0] + bias[col + 0];
                v.y = acc[i][j + 1] + bias[col + 1];
                v.z = acc[i][j + 2] + bias[col + 2];
                v.w = acc[i][j + 3] + bias[col + 3];
                *(float4*)(C + (size_t)row * N + col) = v;
            }
        }
    }
}

// ---------------- row L2-normalize H (16384 x 256), one warp per row ----------------
__global__ void norm_rows_kernel(float* __restrict__ H)
{
    int warp = (blockIdx.x * blockDim.x + threadIdx.x) >> 5;
    int lane = threadIdx.x & 31;
    if (warp >= 16384) return;
    float* rowp = H + (size_t)warp * 256;
    float4 a = *(const float4*)(rowp + lane * 4);
    float4 b = *(const float4*)(rowp + 128 + lane * 4);
    float s = a.x * a.x + a.y * a.y + a.z * a.z + a.w * a.w
            + b.x * b.x + b.y * b.y + b.z * b.z + b.w * b.w;
#pragma unroll
    for (int o = 16; o; o >>= 1) s += __shfl_xor_sync(0xffffffffu, s, o);
    float inv = 1.0f / sqrtf(s);
    a.x *= inv; a.y *= inv; a.z *= inv; a.w *= inv;
    b.x *= inv; b.y *= inv; b.z *= inv; b.w *= inv;
    *(float4*)(rowp + lane * 4) = a;
    *(float4*)(rowp + 128 + lane * 4) = b;
}

// ---------------- scan phase 1: per-class ordered occurrence lists ----------------
// One warp per class. Ballot+popc preserves original label order.
__global__ void rank_kernel(const int* __restrict__ llabel,
                            int* __restrict__ occ, int* __restrict__ cnt)
{
    int c = blockIdx.x;
    int lane = threadIdx.x;
    int base = 0;
    for (int i0 = 0; i0 < 8192; i0 += 32) {
        int lab = llabel[i0 + lane];
        unsigned m = __ballot_sync(0xffffffffu, lab == c);
        if (lab == c) {
            int r = base + __popc(m & ((1u << lane) - 1u));
            occ[c * 8192 + r] = i0 + lane;
        }
        base += __popc(m);
    }
    if (lane == 0) cnt[c] = base;
}

// ---------------- scan phase 2: EMA over each class's occurrences ----------------
__global__ void ema_kernel(const float* __restrict__ H,
                           const int* __restrict__ occ, const int* __restrict__ cnt,
                           const float* __restrict__ mbank0, const float* __restrict__ start0,
                           float* __restrict__ MB, float* __restrict__ out_mbank)
{
    int c = blockIdx.x;       // 0..39
    int d = threadIdx.x;      // 0..255
    __shared__ int idxs[256];
    int n = cnt[c];
    float row = mbank0[c * 256 + d];
    bool started = (start0[c] != 0.0f);
    for (int r0 = 0; r0 < n; r0 += 256) {
        __syncthreads();
        if (r0 + d < n) idxs[d] = occ[c * 8192 + r0 + d];
        __syncthreads();
        int lim = min(256, n - r0);
#pragma unroll 4
        for (int j = 0; j < lim; j++) {
            float f = H[(size_t)idxs[j] * 256 + d];
            row = started ? fmaf(0.9f, row, 0.1f * f) : f;
            started = true;
        }
    }
    MB[c * 256 + d] = row;
    out_mbank[c * 256 + d] = row;
}

// ---------------- distances: lscores for labeled, UF = [ufeat | um | 0pad] ----------------
__global__ void dist_kernel(const float* __restrict__ H, const float* __restrict__ MB,
                            float* __restrict__ lscores, float* __restrict__ UF)
{
    __shared__ float mb[40 * 256];
    for (int i = threadIdx.x; i < 40 * 256; i += blockDim.x) mb[i] = MB[i];
    __syncthreads();

    int nwarp = (gridDim.x * blockDim.x) >> 5;
    int warp = (blockIdx.x * blockDim.x + threadIdx.x) >> 5;
    int lane = threadIdx.x & 31;

    for (int row = warp; row < 16384; row += nwarp) {
        float h[8];
#pragma unroll
        for (int k = 0; k < 8; k++) h[k] = H[(size_t)row * 256 + lane + 32 * k];
        if (row < 8192) {
            float best = 3.4e38f;
            for (int c = 0; c < 40; c++) {
                float s = 0.f;
#pragma unroll
                for (int k = 0; k < 8; k++) {
                    float dl = h[k] - mb[c * 256 + lane + 32 * k];
                    s = fmaf(dl, dl, s);
                }
#pragma unroll
                for (int o = 16; o; o >>= 1) s += __shfl_xor_sync(0xffffffffu, s, o);
                best = fminf(best, s);
            }
            if (lane == 0) lscores[row] = sqrtf(best);
        } else {
            int r = row - 8192;
#pragma unroll
            for (int k = 0; k < 8; k++)
                UF[(size_t)r * 304 + lane + 32 * k] = h[k];
            for (int c = 0; c < 40; c++) {
                float s = 0.f;
#pragma unroll
                for (int k = 0; k < 8; k++) {
                    float dl = h[k] - mb[c * 256 + lane + 32 * k];
                    s = fmaf(dl, dl, s);
                }
#pragma unroll
                for (int o = 16; o; o >>= 1) s += __shfl_xor_sync(0xffffffffu, s, o);
                if (lane == 0) UF[(size_t)r * 304 + 256 + c] = sqrtf(s);
            }
            if (lane < 8) UF[(size_t)r * 304 + 296 + lane] = 0.f;  // zero pad
        }
    }
}

// ---------------- BN stage 1: per-block partial column sums (deterministic) ----------------
__global__ void bn_part_kernel(const float* __restrict__ X, int cols,
                               float* __restrict__ ps, float* __restrict__ pq)
{
    int col = threadIdx.x;          // blockDim.x == cols
    int r0 = blockIdx.x * 128;
    float s = 0.f, q = 0.f;
    for (int r = r0; r < r0 + 128; r++) {
        float v = X[(size_t)r * cols + col];
        s += v;
        q = fmaf(v, v, q);
    }
    ps[blockIdx.x * cols + col] = s;
    pq[blockIdx.x * cols + col] = q;
}

// ---------------- BN stage 2: fold 64 partials -> mean, 1/sqrt(var+eps) ----------------
__global__ void bn_stats_kernel(const float* __restrict__ ps, const float* __restrict__ pq,
                                int cols, float* __restrict__ mean, float* __restrict__ inv)
{
    int col = threadIdx.x;
    float s = 0.f, q = 0.f;
    for (int b = 0; b < 64; b++) { s += ps[b * cols + col]; q += pq[b * cols + col]; }
    float mu = s * (1.0f / 8192.0f);
    float var = q * (1.0f / 8192.0f) - mu * mu;
    mean[col] = mu;
    inv[col] = 1.0f / sqrtf(var + 1e-5f);
}

// ---------------- BN apply + ReLU (in place); cols is a power of two ----------------
__global__ void bn_apply_kernel(float* __restrict__ X, int n, int cols,
                                const float* __restrict__ mean, const float* __restrict__ inv,
                                const float* __restrict__ g, const float* __restrict__ be)
{
    int idx = blockIdx.x * blockDim.x + threadIdx.x;
    if (idx < n) {
        int col = idx & (cols - 1);
        float v = (X[idx] - mean[col]) * inv[col] * g[col] + be[col];
        X[idx] = fmaxf(v, 0.f);
    }
}

// ---------------- final matvec: uscores = U4(8192x64) @ W5(64) + b5 ----------------
__global__ void gemm5_kernel(const float* __restrict__ U4, const float* __restrict__ W5,
                             const float* __restrict__ b5, float* __restrict__ out)
{
    int warp = (blockIdx.x * blockDim.x + threadIdx.x) >> 5;
    int lane = threadIdx.x & 31;
    if (warp >= 8192) return;
    float s = U4[(size_t)warp * 64 + lane] * W5[lane]
            + U4[(size_t)warp * 64 + 32 + lane] * W5[32 + lane];
#pragma unroll
    for (int o = 16; o; o >>= 1) s += __shfl_xor_sync(0xffffffffu, s, o);
    if (lane == 0) out[warp] = s + b5[0];
}

// ---------------- launcher ----------------
extern "C" void kernel_launch(void* const* d_in, const int* in_sizes, int n_in,
                              void* d_out, int out_size)
{
    const float* lufeat = (const float*)d_in[0];
    const int*   llabel = (const int*)  d_in[1];
    const float* W1 = (const float*)d_in[2];
    const float* b1 = (const float*)d_in[3];
    const float* W2 = (const float*)d_in[4];
    const float* b2 = (const float*)d_in[5];
    const float* W3 = (const float*)d_in[6];
    const float* b3 = (const float*)d_in[7];
    const float* W4 = (const float*)d_in[8];
    const float* b4 = (const float*)d_in[9];
    const float* W5 = (const float*)d_in[10];
    const float* b5 = (const float*)d_in[11];
    const float* g1 = (const float*)d_in[12];
    const float* be1 = (const float*)d_in[13];
    const float* g2 = (const float*)d_in[14];
    const float* be2 = (const float*)d_in[15];
    const float* mbank0 = (const float*)d_in[16];
    const float* start0 = (const float*)d_in[17];
    float* out = (float*)d_out;

    float *H1, *H, *MB, *UF, *Y3, *Y4, *PS, *PQ, *MEAN, *INV;
    int *OCC, *CNT;
    cudaGetSymbolAddress((void**)&H1, g_H1);
    cudaGetSymbolAddress((void**)&H,  g_H);
    cudaGetSymbolAddress((void**)&MB, g_MB);
    cudaGetSymbolAddress((void**)&UF, g_UF);
    cudaGetSymbolAddress((void**)&Y3, g_Y3);
    cudaGetSymbolAddress((void**)&Y4, g_Y4);
    cudaGetSymbolAddress((void**)&PS, g_PS);
    cudaGetSymbolAddress((void**)&PQ, g_PQ);
    cudaGetSymbolAddress((void**)&MEAN, g_MEAN);
    cudaGetSymbolAddress((void**)&INV,  g_INV);
    cudaGetSymbolAddress((void**)&OCC, g_OCC);
    cudaGetSymbolAddress((void**)&CNT, g_CNT);

    // occurrence lists depend only on llabel; launch first (overlaps nothing but cheap)
    rank_kernel<<<40, 32>>>(llabel, OCC, CNT);

    // h = (lufeat @ W1 + b1) @ W2 + b2 ; normalize rows
    sgemm_bias_db<<<dim3(4, 128), 256>>>(lufeat, 1024, W1, b1, H1, 16384, 512, 1024);
    sgemm_bias_db<<<dim3(2, 128), 256>>>(H1, 512, W2, b2, H, 16384, 256, 512);
    norm_rows_kernel<<<2048, 256>>>(H);

    // memory bank EMA (parallel over classes; serial chain is only per-class occurrences)
    ema_kernel<<<40, 256>>>(H, OCC, CNT, mbank0, start0, MB, out + 16384);

    // distances: lscores to d_out[0..8191], UF = [ufeat | um | pad]
    dist_kernel<<<128, 256>>>(H, MB, out, UF);

    // layer 3: UF(8192x296, stride 304) @ W3(296x256) + b3 -> BN -> ReLU
    sgemm_bias_db<<<dim3(2, 64), 256>>>(UF, 304, W3, b3, Y3, 8192, 256, 296);
    bn_part_kernel<<<64, 256>>>(Y3, 256, PS, PQ);
    bn_stats_kernel<<<1, 256>>>(PS, PQ, 256, MEAN, INV);
    bn_apply_kernel<<<(8192 * 256 + 255) / 256, 256>>>(Y3, 8192 * 256, 256, MEAN, INV, g1, be1);

    // layer 4: Y3(8192x256) @ W4(256x64) + b4 -> BN -> ReLU
    sgemm_bias_db<<<dim3(1, 64), 256>>>(Y3, 256, W4, b4, Y4, 8192, 64, 256);
    bn_part_kernel<<<64, 64>>>(Y4, 64, PS, PQ);
    bn_stats_kernel<<<1, 64>>>(PS, PQ, 64, MEAN, INV);
    bn_apply_kernel<<<(8192 * 64 + 255) / 256, 256>>>(Y4, 8192 * 64, 64, MEAN, INV, g2, be2);

    // uscores
    gemm5_kernel<<<1024, 256>>>(Y4, W5, b5, out + 8192);
}

// round 10
// speedup vs baseline: 3.1780x; 1.7568x over previous
#include <cuda_runtime.h>
#include <cuda_bf16.h>
#include <cstdint>
#include <math.h>

// ---------------- scratch (device globals; no allocation allowed) ----------------
__device__ float g_H1[16384 * 512];   // lufeat@W1+b1
__device__ float g_H [16384 * 256];   // (..)@W2+b2, then normalized in place
__device__ float g_MB[40 * 256];      // memory bank after scan
__device__ float g_UF[8192 * 320];    // concat(ufeat, um), padded 296->320
__device__ float g_Y3[8192 * 256];
__device__ float g_Y4[8192 * 64];
__device__ float g_PS[64 * 256];
__device__ float g_PQ[64 * 256];
__device__ float g_MEAN[256];
__device__ float g_INV[256];
__device__ int   g_OCC[40 * 8192];
__device__ int   g_CNT[40];
// bf16 hi/lo split weights (padded shapes)
__device__ __align__(16) __nv_bfloat16 g_W1h[1024 * 512], g_W1l[1024 * 512];
__device__ __align__(16) __nv_bfloat16 g_W2h[512 * 256],  g_W2l[512 * 256];
__device__ __align__(16) __nv_bfloat16 g_W3h[320 * 256],  g_W3l[320 * 256];   // K 296->320
__device__ __align__(16) __nv_bfloat16 g_W4h[256 * 128],  g_W4l[256 * 128];   // N 64->128

// ---------------- split weights into bf16 hi/lo with zero padding ----------------
__global__ void split_pad_kernel(const float* __restrict__ W, int K, int N, int Np,
                                 __nv_bfloat16* __restrict__ Wh, __nv_bfloat16* __restrict__ Wl,
                                 int total /* = Kp*Np */)
{
    int idx = blockIdx.x * blockDim.x + threadIdx.x;
    if (idx >= total) return;
    int k = idx / Np, n = idx % Np;
    float v = (n < N && k < K) ? W[k * N + n] : 0.f;
    __nv_bfloat16 h = __float2bfloat16(v);
    float r = v - __bfloat162float(h);
    Wh[idx] = h;
    Wl[idx] = __float2bfloat16(r);
}

// ---------------- bf16-split tensor-core GEMM: C = A(f32) @ B(bf16 hi/lo) + bias ------
// BM=128, BN=128, BK=32. 256 threads = 8 warps (4x2), each warp 32x64.
// M % 128 == 0, K % 32 == 0 (use padded K), B padded to Np columns (no B guards).
__global__ __launch_bounds__(256, 2) void mma_gemm(
    const float* __restrict__ A, int lda,
    const __nv_bfloat16* __restrict__ Bh, const __nv_bfloat16* __restrict__ Bl,
    const float* __restrict__ bias, float* __restrict__ C,
    int N, int Np, int K)
{
    __shared__ __nv_bfloat16 sAh[128][40], sAl[128][40];    // [m][k], stride 40
    __shared__ __nv_bfloat16 sBh[32][136], sBl[32][136];    // [k][n], stride 136

    const int tid = threadIdx.x;
    const int lane = tid & 31, warp = tid >> 5;
    const int g = lane >> 2, tig = lane & 3;
    const int warpM = (warp >> 1) * 32;
    const int warpN = (warp & 1) * 64;
    const int bm = blockIdx.y * 128;
    const int bn = blockIdx.x * 128;

    float acc[2][8][4];
#pragma unroll
    for (int i = 0; i < 2; i++)
#pragma unroll
        for (int j = 0; j < 8; j++)
#pragma unroll
            for (int q = 0; q < 4; q++) acc[i][j][q] = 0.f;

    const int nk = K / 32;

    // global load registers
    float4 ra[4];
    uint4  rbh[2], rbl[2];

    // A mapping: v = tid + 256*i  ->  row = v>>3, col = (v&7)*4
    // B mapping: v = tid + 256*i  ->  k = v>>4, n8 = (v&15)*8  (uint4 = 8 bf16)
    auto load_tile = [&](int k0) {
#pragma unroll
        for (int i = 0; i < 4; i++) {
            int v = tid + 256 * i;
            int r = v >> 3, c = (v & 7) * 4;
            ra[i] = *(const float4*)(A + (size_t)(bm + r) * lda + k0 + c);
        }
#pragma unroll
        for (int i = 0; i < 2; i++) {
            int v = tid + 256 * i;
            int k = v >> 4, n8 = (v & 15) * 8;
            rbh[i] = *(const uint4*)(Bh + (size_t)(k0 + k) * Np + bn + n8);
            rbl[i] = *(const uint4*)(Bl + (size_t)(k0 + k) * Np + bn + n8);
        }
    };

    auto store_tile = [&]() {
#pragma unroll
        for (int i = 0; i < 4; i++) {
            int v = tid + 256 * i;
            int r = v >> 3, c = (v & 7) * 4;
            float f[4] = { ra[i].x, ra[i].y, ra[i].z, ra[i].w };
            __nv_bfloat16 h[4], l[4];
#pragma unroll
            for (int q = 0; q < 4; q++) {
                h[q] = __float2bfloat16(f[q]);
                l[q] = __float2bfloat16(f[q] - __bfloat162float(h[q]));
            }
            __nv_bfloat162 hh0; hh0.x = h[0]; hh0.y = h[1];
            __nv_bfloat162 hh1; hh1.x = h[2]; hh1.y = h[3];
            __nv_bfloat162 ll0; ll0.x = l[0]; ll0.y = l[1];
            __nv_bfloat162 ll1; ll1.x = l[2]; ll1.y = l[3];
            *(__nv_bfloat162*)&sAh[r][c]     = hh0;
            *(__nv_bfloat162*)&sAh[r][c + 2] = hh1;
            *(__nv_bfloat162*)&sAl[r][c]     = ll0;
            *(__nv_bfloat162*)&sAl[r][c + 2] = ll1;
        }
#pragma unroll
        for (int i = 0; i < 2; i++) {
            int v = tid + 256 * i;
            int k = v >> 4, n8 = (v & 15) * 8;
            *(uint4*)&sBh[k][n8] = rbh[i];
            *(uint4*)&sBl[k][n8] = rbl[i];
        }
    };

    load_tile(0);
    store_tile();
    __syncthreads();

    for (int t = 0; t < nk; t++) {
        if (t + 1 < nk) load_tile((t + 1) * 32);

#pragma unroll
        for (int kk = 0; kk < 32; kk += 16) {
            // A fragments (hi and lo)
            unsigned int ah[2][4], al[2][4];
#pragma unroll
            for (int i = 0; i < 2; i++) {
                int r0 = warpM + i * 16 + g;
                int c0 = kk + tig * 2;
                ah[i][0] = *(const unsigned int*)&sAh[r0][c0];
                ah[i][1] = *(const unsigned int*)&sAh[r0 + 8][c0];
                ah[i][2] = *(const unsigned int*)&sAh[r0][c0 + 8];
                ah[i][3] = *(const unsigned int*)&sAh[r0 + 8][c0 + 8];
                al[i][0] = *(const unsigned int*)&sAl[r0][c0];
                al[i][1] = *(const unsigned int*)&sAl[r0 + 8][c0];
                al[i][2] = *(const unsigned int*)&sAl[r0][c0 + 8];
                al[i][3] = *(const unsigned int*)&sAl[r0 + 8][c0 + 8];
            }
#pragma unroll
            for (int j = 0; j < 8; j++) {
                int n0 = warpN + j * 8 + g;
                int kb = kk + tig * 2;
                __nv_bfloat162 th0, th1, tl0, tl1;
                th0.x = sBh[kb][n0];     th0.y = sBh[kb + 1][n0];
                th1.x = sBh[kb + 8][n0]; th1.y = sBh[kb + 9][n0];
                tl0.x = sBl[kb][n0];     tl0.y = sBl[kb + 1][n0];
                tl1.x = sBl[kb + 8][n0]; tl1.y = sBl[kb + 9][n0];
                unsigned int bh0 = *(unsigned int*)&th0;
                unsigned int bh1 = *(unsigned int*)&th1;
                unsigned int bl0 = *(unsigned int*)&tl0;
                unsigned int bl1 = *(unsigned int*)&tl1;
#pragma unroll
                for (int i = 0; i < 2; i++) {
                    float* d = acc[i][j];
                    asm volatile(
                        "mma.sync.aligned.m16n8k16.row.col.f32.bf16.bf16.f32 "
                        "{%0,%1,%2,%3}, {%4,%5,%6,%7}, {%8,%9}, {%0,%1,%2,%3};"
                        : "+f"(d[0]), "+f"(d[1]), "+f"(d[2]), "+f"(d[3])
                        : "r"(ah[i][0]), "r"(ah[i][1]), "r"(ah[i][2]), "r"(ah[i][3]),
                          "r"(bh0), "r"(bh1));
                    asm volatile(
                        "mma.sync.aligned.m16n8k16.row.col.f32.bf16.bf16.f32 "
                        "{%0,%1,%2,%3}, {%4,%5,%6,%7}, {%8,%9}, {%0,%1,%2,%3};"
                        : "+f"(d[0]), "+f"(d[1]), "+f"(d[2]), "+f"(d[3])
                        : "r"(ah[i][0]), "r"(ah[i][1]), "r"(ah[i][2]), "r"(ah[i][3]),
                          "r"(bl0), "r"(bl1));
                    asm volatile(
                        "mma.sync.aligned.m16n8k16.row.col.f32.bf16.bf16.f32 "
                        "{%0,%1,%2,%3}, {%4,%5,%6,%7}, {%8,%9}, {%0,%1,%2,%3};"
                        : "+f"(d[0]), "+f"(d[1]), "+f"(d[2]), "+f"(d[3])
                        : "r"(al[i][0]), "r"(al[i][1]), "r"(al[i][2]), "r"(al[i][3]),
                          "r"(bh0), "r"(bh1));
                }
            }
        }
        __syncthreads();
        if (t + 1 < nk) {
            store_tile();
        }
        __syncthreads();
    }

    // epilogue: c0,c1 -> row r, cols c..c+1 ; c2,c3 -> row r+8
#pragma unroll
    for (int i = 0; i < 2; i++) {
        int r = bm + warpM + i * 16 + g;
#pragma unroll
        for (int j = 0; j < 8; j++) {
            int c = bn + warpN + j * 8 + tig * 2;
            if (c < N) {
                float2 v0 = make_float2(acc[i][j][0] + bias[c], acc[i][j][1] + bias[c + 1]);
                float2 v1 = make_float2(acc[i][j][2] + bias[c], acc[i][j][3] + bias[c + 1]);
                *(float2*)(C + (size_t)r * N + c) = v0;
                *(float2*)(C + (size_t)(r + 8) * N + c) = v1;
            }
        }
    }
}

// ---------------- row L2-normalize H (16384 x 256), one warp per row ----------------
__global__ void norm_rows_kernel(float* __restrict__ H)
{
    int warp = (blockIdx.x * blockDim.x + threadIdx.x) >> 5;
    int lane = threadIdx.x & 31;
    if (warp >= 16384) return;
    float* rowp = H + (size_t)warp * 256;
    float4 a = *(const float4*)(rowp + lane * 4);
    float4 b = *(const float4*)(rowp + 128 + lane * 4);
    float s = a.x * a.x + a.y * a.y + a.z * a.z + a.w * a.w
            + b.x * b.x + b.y * b.y + b.z * b.z + b.w * b.w;
#pragma unroll
    for (int o = 16; o; o >>= 1) s += __shfl_xor_sync(0xffffffffu, s, o);
    float inv = 1.0f / sqrtf(s);
    a.x *= inv; a.y *= inv; a.z *= inv; a.w *= inv;
    b.x *= inv; b.y *= inv; b.z *= inv; b.w *= inv;
    *(float4*)(rowp + lane * 4) = a;
    *(float4*)(rowp + 128 + lane * 4) = b;
}

// ---------------- scan phase 1: per-class ordered occurrence lists ----------------
__global__ void rank_kernel(const int* __restrict__ llabel,
                            int* __restrict__ occ, int* __restrict__ cnt)
{
    int c = blockIdx.x;
    int lane = threadIdx.x;
    int base = 0;
    for (int i0 = 0; i0 < 8192; i0 += 32) {
        int lab = llabel[i0 + lane];
        unsigned m = __ballot_sync(0xffffffffu, lab == c);
        if (lab == c) {
            int r = base + __popc(m & ((1u << lane) - 1u));
            occ[c * 8192 + r] = i0 + lane;
        }
        base += __popc(m);
    }
    if (lane == 0) cnt[c] = base;
}

// ---------------- scan phase 2: EMA over each class's occurrences ----------------
__global__ void ema_kernel(const float* __restrict__ H,
                           const int* __restrict__ occ, const int* __restrict__ cnt,
                           const float* __restrict__ mbank0, const float* __restrict__ start0,
                           float* __restrict__ MB, float* __restrict__ out_mbank)
{
    int c = blockIdx.x;
    int d = threadIdx.x;
    __shared__ int idxs[256];
    int n = cnt[c];
    float row = mbank0[c * 256 + d];
    bool started = (start0[c] != 0.0f);
    for (int r0 = 0; r0 < n; r0 += 256) {
        __syncthreads();
        if (r0 + d < n) idxs[d] = occ[c * 8192 + r0 + d];
        __syncthreads();
        int lim = min(256, n - r0);
#pragma unroll 4
        for (int j = 0; j < lim; j++) {
            float f = H[(size_t)idxs[j] * 256 + d];
            row = started ? fmaf(0.9f, row, 0.1f * f) : f;
            started = true;
        }
    }
    MB[c * 256 + d] = row;
    out_mbank[c * 256 + d] = row;
}

// ---------------- distances: lscores for labeled, UF = [ufeat | um | 0pad] ----------------
__global__ void dist_kernel(const float* __restrict__ H, const float* __restrict__ MB,
                            float* __restrict__ lscores, float* __restrict__ UF)
{
    __shared__ float mb[40 * 256];
    for (int i = threadIdx.x; i < 40 * 256; i += blockDim.x) mb[i] = MB[i];
    __syncthreads();

    int nwarp = (gridDim.x * blockDim.x) >> 5;
    int warp = (blockIdx.x * blockDim.x + threadIdx.x) >> 5;
    int lane = threadIdx.x & 31;

    for (int row = warp; row < 16384; row += nwarp) {
        float h[8];
#pragma unroll
        for (int k = 0; k < 8; k++) h[k] = H[(size_t)row * 256 + lane + 32 * k];
        if (row < 8192) {
            float best = 3.4e38f;
            for (int c = 0; c < 40; c++) {
                float s = 0.f;
#pragma unroll
                for (int k = 0; k < 8; k++) {
                    float dl = h[k] - mb[c * 256 + lane + 32 * k];
                    s = fmaf(dl, dl, s);
                }
#pragma unroll
                for (int o = 16; o; o >>= 1) s += __shfl_xor_sync(0xffffffffu, s, o);
                best = fminf(best, s);
            }
            if (lane == 0) lscores[row] = sqrtf(best);
        } else {
            int r = row - 8192;
#pragma unroll
            for (int k = 0; k < 8; k++)
                UF[(size_t)r * 320 + lane + 32 * k] = h[k];
            for (int c = 0; c < 40; c++) {
                float s = 0.f;
#pragma unroll
                for (int k = 0; k < 8; k++) {
                    float dl = h[k] - mb[c * 256 + lane + 32 * k];
                    s = fmaf(dl, dl, s);
                }
#pragma unroll
                for (int o = 16; o; o >>= 1) s += __shfl_xor_sync(0xffffffffu, s, o);
                if (lane == 0) UF[(size_t)r * 320 + 256 + c] = sqrtf(s);
            }
            if (lane < 24) UF[(size_t)r * 320 + 296 + lane] = 0.f;  // zero pad 296..319
        }
    }
}

// ---------------- BN stage 1: per-block partial column sums (deterministic) ----------------
__global__ void bn_part_kernel(const float* __restrict__ X, int cols,
                               float* __restrict__ ps, float* __restrict__ pq)
{
    int col = threadIdx.x;
    int r0 = blockIdx.x * 128;
    float s = 0.f, q = 0.f;
    for (int r = r0; r < r0 + 128; r++) {
        float v = X[(size_t)r * cols + col];
        s += v;
        q = fmaf(v, v, q);
    }
    ps[blockIdx.x * cols + col] = s;
    pq[blockIdx.x * cols + col] = q;
}

// ---------------- BN stage 2: fold 64 partials ----------------
__global__ void bn_stats_kernel(const float* __restrict__ ps, const float* __restrict__ pq,
                                int cols, float* __restrict__ mean, float* __restrict__ inv)
{
    int col = threadIdx.x;
    float s = 0.f, q = 0.f;
    for (int b = 0; b < 64; b++) { s += ps[b * cols + col]; q += pq[b * cols + col]; }
    float mu = s * (1.0f / 8192.0f);
    float var = q * (1.0f / 8192.0f) - mu * mu;
    mean[col] = mu;
    inv[col] = 1.0f / sqrtf(var + 1e-5f);
}

// ---------------- BN apply + ReLU (in place) ----------------
__global__ void bn_apply_kernel(float* __restrict__ X, int n, int cols,
                                const float* __restrict__ mean, const float* __restrict__ inv,
                                const float* __restrict__ g, const float* __restrict__ be)
{
    int idx = blockIdx.x * blockDim.x + threadIdx.x;
    if (idx < n) {
        int col = idx & (cols - 1);
        float v = (X[idx] - mean[col]) * inv[col] * g[col] + be[col];
        X[idx] = fmaxf(v, 0.f);
    }
}

// ---------------- final matvec ----------------
__global__ void gemm5_kernel(const float* __restrict__ U4, const float* __restrict__ W5,
                             const float* __restrict__ b5, float* __restrict__ out)
{
    int warp = (blockIdx.x * blockDim.x + threadIdx.x) >> 5;
    int lane = threadIdx.x & 31;
    if (warp >= 8192) return;
    float s = U4[(size_t)warp * 64 + lane] * W5[lane]
            + U4[(size_t)warp * 64 + 32 + lane] * W5[32 + lane];
#pragma unroll
    for (int o = 16; o; o >>= 1) s += __shfl_xor_sync(0xffffffffu, s, o);
    if (lane == 0) out[warp] = s + b5[0];
}

// ---------------- launcher ----------------
extern "C" void kernel_launch(void* const* d_in, const int* in_sizes, int n_in,
                              void* d_out, int out_size)
{
    const float* lufeat = (const float*)d_in[0];
    const int*   llabel = (const int*)  d_in[1];
    const float* W1 = (const float*)d_in[2];
    const float* b1 = (const float*)d_in[3];
    const float* W2 = (const float*)d_in[4];
    const float* b2 = (const float*)d_in[5];
    const float* W3 = (const float*)d_in[6];
    const float* b3 = (const float*)d_in[7];
    const float* W4 = (const float*)d_in[8];
    const float* b4 = (const float*)d_in[9];
    const float* W5 = (const float*)d_in[10];
    const float* b5 = (const float*)d_in[11];
    const float* g1 = (const float*)d_in[12];
    const float* be1 = (const float*)d_in[13];
    const float* g2 = (const float*)d_in[14];
    const float* be2 = (const float*)d_in[15];
    const float* mbank0 = (const float*)d_in[16];
    const float* start0 = (const float*)d_in[17];
    float* out = (float*)d_out;

    float *H1, *H, *MB, *UF, *Y3, *Y4, *PS, *PQ, *MEAN, *INV;
    int *OCC, *CNT;
    __nv_bfloat16 *W1h, *W1l, *W2h, *W2l, *W3h, *W3l, *W4h, *W4l;
    cudaGetSymbolAddress((void**)&H1, g_H1);
    cudaGetSymbolAddress((void**)&H,  g_H);
    cudaGetSymbolAddress((void**)&MB, g_MB);
    cudaGetSymbolAddress((void**)&UF, g_UF);
    cudaGetSymbolAddress((void**)&Y3, g_Y3);
    cudaGetSymbolAddress((void**)&Y4, g_Y4);
    cudaGetSymbolAddress((void**)&PS, g_PS);
    cudaGetSymbolAddress((void**)&PQ, g_PQ);
    cudaGetSymbolAddress((void**)&MEAN, g_MEAN);
    cudaGetSymbolAddress((void**)&INV,  g_INV);
    cudaGetSymbolAddress((void**)&OCC, g_OCC);
    cudaGetSymbolAddress((void**)&CNT, g_CNT);
    cudaGetSymbolAddress((void**)&W1h, g_W1h); cudaGetSymbolAddress((void**)&W1l, g_W1l);
    cudaGetSymbolAddress((void**)&W2h, g_W2h); cudaGetSymbolAddress((void**)&W2l, g_W2l);
    cudaGetSymbolAddress((void**)&W3h, g_W3h); cudaGetSymbolAddress((void**)&W3l, g_W3l);
    cudaGetSymbolAddress((void**)&W4h, g_W4h); cudaGetSymbolAddress((void**)&W4l, g_W4l);

    // weight splits (cheap; once per launch)
    split_pad_kernel<<<(1024 * 512 + 255) / 256, 256>>>(W1, 1024, 512, 512, W1h, W1l, 1024 * 512);
    split_pad_kernel<<<(512 * 256 + 255) / 256, 256>>>(W2, 512, 256, 256, W2h, W2l, 512 * 256);
    split_pad_kernel<<<(320 * 256 + 255) / 256, 256>>>(W3, 296, 256, 256, W3h, W3l, 320 * 256);
    split_pad_kernel<<<(256 * 128 + 255) / 256, 256>>>(W4, 256, 64, 128, W4h, W4l, 256 * 128);

    rank_kernel<<<40, 32>>>(llabel, OCC, CNT);

    // h = (lufeat @ W1 + b1) @ W2 + b2 ; normalize rows
    mma_gemm<<<dim3(4, 128), 256>>>(lufeat, 1024, W1h, W1l, b1, H1, 512, 512, 1024);
    mma_gemm<<<dim3(2, 128), 256>>>(H1, 512, W2h, W2l, b2, H, 256, 256, 512);
    norm_rows_kernel<<<2048, 256>>>(H);

    // memory bank EMA
    ema_kernel<<<40, 256>>>(H, OCC, CNT, mbank0, start0, MB, out + 16384);

    // distances
    dist_kernel<<<128, 256>>>(H, MB, out, UF);

    // layer 3: UF(8192x296, stride 320, zero-padded) @ W3(padded 320x256)
    mma_gemm<<<dim3(2, 64), 256>>>(UF, 320, W3h, W3l, b3, Y3, 256, 256, 320);
    bn_part_kernel<<<64, 256>>>(Y3, 256, PS, PQ);
    bn_stats_kernel<<<1, 256>>>(PS, PQ, 256, MEAN, INV);
    bn_apply_kernel<<<(8192 * 256 + 255) / 256, 256>>>(Y3, 8192 * 256, 256, MEAN, INV, g1, be1);

    // layer 4: Y3(8192x256) @ W4(padded 256x128)
    mma_gemm<<<dim3(1, 64), 256>>>(Y3, 256, W4h, W4l, b4, Y4, 64, 128, 256);
    bn_part_kernel<<<64, 64>>>(Y4, 64, PS, PQ);
    bn_stats_kernel<<<1, 64>>>(PS, PQ, 64, MEAN, INV);
    bn_apply_kernel<<<(8192 * 64 + 255) / 256, 256>>>(Y4, 8192 * 64, 64, MEAN, INV, g2, be2);

    // uscores
    gemm5_kernel<<<1024, 256>>>(Y4, W5, b5, out + 8192);
}

// round 13
// speedup vs baseline: 3.5408x; 1.1142x over previous
#include <cuda_runtime.h>
#include <cuda_bf16.h>
#include <cstdint>
#include <math.h>

// ---------------- scratch (device globals; no allocation allowed) ----------------
__device__ float g_H1[16384 * 512];   // lufeat@W1+b1
__device__ float g_H [16384 * 256];   // (..)@W2+b2, then normalized in place
__device__ float g_MB[40 * 256];      // memory bank after scan
__device__ float g_UF[8192 * 320];    // concat(ufeat, um), padded 296->320
__device__ float g_Y3[8192 * 256];
__device__ float g_Y4[8192 * 64];
__device__ float g_PS[64 * 256];
__device__ float g_PQ[64 * 256];
__device__ float g_MEAN[256];
__device__ float g_INV[256];
__device__ int   g_OCC[40 * 8192];
__device__ int   g_CNT[40];
// bf16 hi/lo split weights, TRANSPOSED layout: W^T[n][k], row stride = Kp
__device__ __align__(16) __nv_bfloat16 g_W1h[512 * 1024], g_W1l[512 * 1024];  // [512 n][1024 k]
__device__ __align__(16) __nv_bfloat16 g_W2h[256 * 512],  g_W2l[256 * 512];   // [256][512]
__device__ __align__(16) __nv_bfloat16 g_W3h[256 * 320],  g_W3l[256 * 320];   // [256][320] (K pad 296->320)
__device__ __align__(16) __nv_bfloat16 g_W4h[128 * 256],  g_W4l[128 * 256];   // [128][256] (N pad 64->128)

// ---------------- fused: split all weights into transposed bf16 hi/lo ----------------
__global__ void split_all_kernel(
    const float* __restrict__ W1, const float* __restrict__ W2,
    const float* __restrict__ W3, const float* __restrict__ W4,
    __nv_bfloat16* __restrict__ W1h, __nv_bfloat16* __restrict__ W1l,
    __nv_bfloat16* __restrict__ W2h, __nv_bfloat16* __restrict__ W2l,
    __nv_bfloat16* __restrict__ W3h, __nv_bfloat16* __restrict__ W3l,
    __nv_bfloat16* __restrict__ W4h, __nv_bfloat16* __restrict__ W4l)
{
    int b = blockIdx.x;
    const float* W; __nv_bfloat16 *Wh, *Wl; int K, N, Kp, idx0;
    if (b < 2048)      { W = W1; Wh = W1h; Wl = W1l; K = 1024; N = 512; Kp = 1024; idx0 = b * 256; }
    else if (b < 2560) { W = W2; Wh = W2h; Wl = W2l; K = 512;  N = 256; Kp = 512;  idx0 = (b - 2048) * 256; }
    else if (b < 2880) { W = W3; Wh = W3h; Wl = W3l; K = 296;  N = 256; Kp = 320;  idx0 = (b - 2560) * 256; }
    else               { W = W4; Wh = W4h; Wl = W4l; K = 256;  N = 64;  Kp = 256;  idx0 = (b - 2880) * 256; }
    int idx = idx0 + threadIdx.x;
    int n = idx / Kp, k = idx - n * Kp;
    float v = (k < K && n < N) ? W[k * N + n] : 0.f;
    __nv_bfloat16 h = __float2bfloat16(v);
    float r = v - __bfloat162float(h);
    Wh[idx] = h;
    Wl[idx] = __float2bfloat16(r);
}

// ---------------- bf16-split tensor-core GEMM: C = A(f32) @ B + bias ------------------
// B given TRANSPOSED (B^T[n][k], row stride Kp). BM=128, BN=128, BK=32.
// 256 threads = 8 warps (4x2), each warp 32x64. M % 128 == 0, Kp % 32 == 0,
// A has lda >= Kp with zero pad, B^T zero-padded. Double-buffered smem + cp.async.
__global__ __launch_bounds__(256, 2) void mma_gemm(
    const float* __restrict__ A, int lda,
    const __nv_bfloat16* __restrict__ BhT, const __nv_bfloat16* __restrict__ BlT,
    const float* __restrict__ bias, float* __restrict__ C,
    int N, int Kp)
{
    extern __shared__ __nv_bfloat16 sm[];
    __nv_bfloat16* sAh = sm;            // [2][128][40]
    __nv_bfloat16* sAl = sm + 10240;
    __nv_bfloat16* sBh = sm + 20480;    // [2][128 n][40 k]
    __nv_bfloat16* sBl = sm + 30720;

    const int tid = threadIdx.x;
    const int lane = tid & 31, warp = tid >> 5;
    const int g = lane >> 2, tig = lane & 3;
    const int warpM = (warp >> 1) * 32;
    const int warpN = (warp & 1) * 64;
    const int bm = blockIdx.y * 128;
    const int bn = blockIdx.x * 128;

    float acc[2][8][4];
#pragma unroll
    for (int i = 0; i < 2; i++)
#pragma unroll
        for (int j = 0; j < 8; j++)
#pragma unroll
            for (int q = 0; q < 4; q++) acc[i][j][q] = 0.f;

    const int nk = Kp / 32;
    float4 ra[4];

    // A: v = tid + 256*i -> row = v>>3, col = (v&7)*4
    auto loadA = [&](int k0) {
#pragma unroll
        for (int i = 0; i < 4; i++) {
            int v = tid + 256 * i;
            int r = v >> 3, c = (v & 7) * 4;
            ra[i] = *(const float4*)(A + (size_t)(bm + r) * lda + k0 + c);
        }
    };
    auto storeA = [&](int buf) {
        __nv_bfloat16* dh = sAh + buf * 5120;
        __nv_bfloat16* dl = sAl + buf * 5120;
#pragma unroll
        for (int i = 0; i < 4; i++) {
            int v = tid + 256 * i;
            int r = v >> 3, c = (v & 7) * 4;
            float f[4] = { ra[i].x, ra[i].y, ra[i].z, ra[i].w };
            __nv_bfloat16 h[4], l[4];
#pragma unroll
            for (int q = 0; q < 4; q++) {
                h[q] = __float2bfloat16(f[q]);
                l[q] = __float2bfloat16(f[q] - __bfloat162float(h[q]));
            }
            __nv_bfloat162 hh0; hh0.x = h[0]; hh0.y = h[1];
            __nv_bfloat162 hh1; hh1.x = h[2]; hh1.y = h[3];
            __nv_bfloat162 ll0; ll0.x = l[0]; ll0.y = l[1];
            __nv_bfloat162 ll1; ll1.x = l[2]; ll1.y = l[3];
            *(__nv_bfloat162*)&dh[r * 40 + c]     = hh0;
            *(__nv_bfloat162*)&dh[r * 40 + c + 2] = hh1;
            *(__nv_bfloat162*)&dl[r * 40 + c]     = ll0;
            *(__nv_bfloat162*)&dl[r * 40 + c + 2] = ll1;
        }
    };
    // B: v = tid + 256*i -> n = v>>2, kc = (v&3)*8 ; 16B cp.async each, hi+lo
    auto cpB = [&](int k0, int buf) {
#pragma unroll
        for (int i = 0; i < 2; i++) {
            int v = tid + 256 * i;
            int n = v >> 2, kc = (v & 3) * 8;
            const __nv_bfloat16* gh = BhT + (size_t)(bn + n) * Kp + k0 + kc;
            const __nv_bfloat16* gl = BlT + (size_t)(bn + n) * Kp + k0 + kc;
            unsigned dsth = (unsigned)__cvta_generic_to_shared(&sBh[buf * 5120 + n * 40 + kc]);
            unsigned dstl = (unsigned)__cvta_generic_to_shared(&sBl[buf * 5120 + n * 40 + kc]);
            asm volatile("cp.async.ca.shared.global [%0], [%1], 16;" :: "r"(dsth), "l"(gh));
            asm volatile("cp.async.ca.shared.global [%0], [%1], 16;" :: "r"(dstl), "l"(gl));
        }
        asm volatile("cp.async.commit_group;");
    };

    // prologue
    loadA(0);
    cpB(0, 0);
    storeA(0);
    asm volatile("cp.async.wait_group 0;");
    __syncthreads();

    for (int t = 0; t < nk; t++) {
        int cur = t & 1, nxt = cur ^ 1;
        bool more = (t + 1 < nk);
        if (more) {
            loadA((t + 1) * 32);
            cpB((t + 1) * 32, nxt);
        }

        const __nv_bfloat16* pAh = sAh + cur * 5120;
        const __nv_bfloat16* pAl = sAl + cur * 5120;
        const __nv_bfloat16* pBh = sBh + cur * 5120;
        const __nv_bfloat16* pBl = sBl + cur * 5120;

#pragma unroll
        for (int kk = 0; kk < 32; kk += 16) {
            unsigned int ah[2][4], al[2][4];
#pragma unroll
            for (int i = 0; i < 2; i++) {
                int r0 = warpM + i * 16 + g;
                int c0 = kk + tig * 2;
                ah[i][0] = *(const unsigned int*)&pAh[r0 * 40 + c0];
                ah[i][1] = *(const unsigned int*)&pAh[(r0 + 8) * 40 + c0];
                ah[i][2] = *(const unsigned int*)&pAh[r0 * 40 + c0 + 8];
                ah[i][3] = *(const unsigned int*)&pAh[(r0 + 8) * 40 + c0 + 8];
                al[i][0] = *(const unsigned int*)&pAl[r0 * 40 + c0];
                al[i][1] = *(const unsigned int*)&pAl[(r0 + 8) * 40 + c0];
                al[i][2] = *(const unsigned int*)&pAl[r0 * 40 + c0 + 8];
                al[i][3] = *(const unsigned int*)&pAl[(r0 + 8) * 40 + c0 + 8];
            }
#pragma unroll
            for (int j = 0; j < 8; j++) {
                int n0 = warpN + j * 8 + g;
                int kb = kk + tig * 2;
                unsigned int bh0 = *(const unsigned int*)&pBh[n0 * 40 + kb];
                unsigned int bh1 = *(const unsigned int*)&pBh[n0 * 40 + kb + 8];
                unsigned int bl0 = *(const unsigned int*)&pBl[n0 * 40 + kb];
                unsigned int bl1 = *(const unsigned int*)&pBl[n0 * 40 + kb + 8];
#pragma unroll
                for (int i = 0; i < 2; i++) {
                    float* d = acc[i][j];
                    asm volatile(
                        "mma.sync.aligned.m16n8k16.row.col.f32.bf16.bf16.f32 "
                        "{%0,%1,%2,%3}, {%4,%5,%6,%7}, {%8,%9}, {%0,%1,%2,%3};"
                        : "+f"(d[0]), "+f"(d[1]), "+f"(d[2]), "+f"(d[3])
                        : "r"(ah[i][0]), "r"(ah[i][1]), "r"(ah[i][2]), "r"(ah[i][3]),
                          "r"(bh0), "r"(bh1));
                    asm volatile(
                        "mma.sync.aligned.m16n8k16.row.col.f32.bf16.bf16.f32 "
                        "{%0,%1,%2,%3}, {%4,%5,%6,%7}, {%8,%9}, {%0,%1,%2,%3};"
                        : "+f"(d[0]), "+f"(d[1]), "+f"(d[2]), "+f"(d[3])
                        : "r"(ah[i][0]), "r"(ah[i][1]), "r"(ah[i][2]), "r"(ah[i][3]),
                          "r"(bl0), "r"(bl1));
                    asm volatile(
                        "mma.sync.aligned.m16n8k16.row.col.f32.bf16.bf16.f32 "
                        "{%0,%1,%2,%3}, {%4,%5,%6,%7}, {%8,%9}, {%0,%1,%2,%3};"
                        : "+f"(d[0]), "+f"(d[1]), "+f"(d[2]), "+f"(d[3])
                        : "r"(al[i][0]), "r"(al[i][1]), "r"(al[i][2]), "r"(al[i][3]),
                          "r"(bh0), "r"(bh1));
                }
            }
        }

        if (more) {
            storeA(nxt);
            asm volatile("cp.async.wait_group 0;");
        }
        __syncthreads();
    }

    // epilogue
#pragma unroll
    for (int i = 0; i < 2; i++) {
        int r = bm + warpM + i * 16 + g;
#pragma unroll
        for (int j = 0; j < 8; j++) {
            int c = bn + warpN + j * 8 + tig * 2;
            if (c < N) {
                float2 v0 = make_float2(acc[i][j][0] + bias[c], acc[i][j][1] + bias[c + 1]);
                float2 v1 = make_float2(acc[i][j][2] + bias[c], acc[i][j][3] + bias[c + 1]);
                *(float2*)(C + (size_t)r * N + c) = v0;
                *(float2*)(C + (size_t)(r + 8) * N + c) = v1;
            }
        }
    }
}

// ---------------- row L2-normalize H (16384 x 256), one warp per row ----------------
__global__ void norm_rows_kernel(float* __restrict__ H)
{
    int warp = (blockIdx.x * blockDim.x + threadIdx.x) >> 5;
    int lane = threadIdx.x & 31;
    if (warp >= 16384) return;
    float* rowp = H + (size_t)warp * 256;
    float4 a = *(const float4*)(rowp + lane * 4);
    float4 b = *(const float4*)(rowp + 128 + lane * 4);
    float s = a.x * a.x + a.y * a.y + a.z * a.z + a.w * a.w
            + b.x * b.x + b.y * b.y + b.z * b.z + b.w * b.w;
#pragma unroll
    for (int o = 16; o; o >>= 1) s += __shfl_xor_sync(0xffffffffu, s, o);
    float inv = 1.0f / sqrtf(s);
    a.x *= inv; a.y *= inv; a.z *= inv; a.w *= inv;
    b.x *= inv; b.y *= inv; b.z *= inv; b.w *= inv;
    *(float4*)(rowp + lane * 4) = a;
    *(float4*)(rowp + 128 + lane * 4) = b;
}

// ---------------- scan phase 1: per-class ordered occurrence lists ----------------
__global__ void rank_kernel(const int* __restrict__ llabel,
                            int* __restrict__ occ, int* __restrict__ cnt)
{
    int c = blockIdx.x;
    int lane = threadIdx.x;
    int base = 0;
    for (int i0 = 0; i0 < 8192; i0 += 32) {
        int lab = llabel[i0 + lane];
        unsigned m = __ballot_sync(0xffffffffu, lab == c);
        if (lab == c) {
            int r = base + __popc(m & ((1u << lane) - 1u));
            occ[c * 8192 + r] = i0 + lane;
        }
        base += __popc(m);
    }
    if (lane == 0) cnt[c] = base;
}

// ---------------- scan phase 2: EMA over each class's occurrences ----------------
__global__ void ema_kernel(const float* __restrict__ H,
                           const int* __restrict__ occ, const int* __restrict__ cnt,
                           const float* __restrict__ mbank0, const float* __restrict__ start0,
                           float* __restrict__ MB, float* __restrict__ out_mbank)
{
    int c = blockIdx.x;
    int d = threadIdx.x;
    __shared__ int idxs[256];
    int n = cnt[c];
    float row = mbank0[c * 256 + d];
    bool started = (start0[c] != 0.0f);
    for (int r0 = 0; r0 < n; r0 += 256) {
        __syncthreads();
        if (r0 + d < n) idxs[d] = occ[c * 8192 + r0 + d];
        __syncthreads();
        int lim = min(256, n - r0);
#pragma unroll 4
        for (int j = 0; j < lim; j++) {
            float f = H[(size_t)idxs[j] * 256 + d];
            row = started ? fmaf(0.9f, row, 0.1f * f) : f;
            started = true;
        }
    }
    MB[c * 256 + d] = row;
    out_mbank[c * 256 + d] = row;
}

// ---------------- distances: lscores for labeled, UF = [ufeat | um | 0pad] ----------------
__global__ void dist_kernel(const float* __restrict__ H, const float* __restrict__ MB,
                            float* __restrict__ lscores, float* __restrict__ UF)
{
    __shared__ float mb[40 * 256];
    for (int i = threadIdx.x; i < 40 * 256; i += blockDim.x) mb[i] = MB[i];
    __syncthreads();

    int nwarp = (gridDim.x * blockDim.x) >> 5;
    int warp = (blockIdx.x * blockDim.x + threadIdx.x) >> 5;
    int lane = threadIdx.x & 31;

    for (int row = warp; row < 16384; row += nwarp) {
        float h[8];
#pragma unroll
        for (int k = 0; k < 8; k++) h[k] = H[(size_t)row * 256 + lane + 32 * k];
        if (row < 8192) {
            float best = 3.4e38f;
            for (int c = 0; c < 40; c++) {
                float s = 0.f;
#pragma unroll
                for (int k = 0; k < 8; k++) {
                    float dl = h[k] - mb[c * 256 + lane + 32 * k];
                    s = fmaf(dl, dl, s);
                }
#pragma unroll
                for (int o = 16; o; o >>= 1) s += __shfl_xor_sync(0xffffffffu, s, o);
                best = fminf(best, s);
            }
            if (lane == 0) lscores[row] = sqrtf(best);
        } else {
            int r = row - 8192;
#pragma unroll
            for (int k = 0; k < 8; k++)
                UF[(size_t)r * 320 + lane + 32 * k] = h[k];
            for (int c = 0; c < 40; c++) {
                float s = 0.f;
#pragma unroll
                for (int k = 0; k < 8; k++) {
                    float dl = h[k] - mb[c * 256 + lane + 32 * k];
                    s = fmaf(dl, dl, s);
                }
#pragma unroll
                for (int o = 16; o; o >>= 1) s += __shfl_xor_sync(0xffffffffu, s, o);
                if (lane == 0) UF[(size_t)r * 320 + 256 + c] = sqrtf(s);
            }
            if (lane < 24) UF[(size_t)r * 320 + 296 + lane] = 0.f;  // zero pad 296..319
        }
    }
}

// ---------------- BN stage 1: per-block partial column sums (deterministic) ----------------
__global__ void bn_part_kernel(const float* __restrict__ X, int cols,
                               float* __restrict__ ps, float* __restrict__ pq)
{
    int col = threadIdx.x;
    int r0 = blockIdx.x * 128;
    float s = 0.f, q = 0.f;
    for (int r = r0; r < r0 + 128; r++) {
        float v = X[(size_t)r * cols + col];
        s += v;
        q = fmaf(v, v, q);
    }
    ps[blockIdx.x * cols + col] = s;
    pq[blockIdx.x * cols + col] = q;
}

// ---------------- BN stage 2: fold 64 partials ----------------
__global__ void bn_stats_kernel(const float* __restrict__ ps, const float* __restrict__ pq,
                                int cols, float* __restrict__ mean, float* __restrict__ inv)
{
    int col = threadIdx.x;
    float s = 0.f, q = 0.f;
    for (int b = 0; b < 64; b++) { s += ps[b * cols + col]; q += pq[b * cols + col]; }
    float mu = s * (1.0f / 8192.0f);
    float var = q * (1.0f / 8192.0f) - mu * mu;
    mean[col] = mu;
    inv[col] = 1.0f / sqrtf(var + 1e-5f);
}

// ---------------- BN apply + ReLU (in place) ----------------
__global__ void bn_apply_kernel(float* __restrict__ X, int n, int cols,
                                const float* __restrict__ mean, const float* __restrict__ inv,
                                const float* __restrict__ g, const float* __restrict__ be)
{
    int idx = blockIdx.x * blockDim.x + threadIdx.x;
    if (idx < n) {
        int col = idx & (cols - 1);
        float v = (X[idx] - mean[col]) * inv[col] * g[col] + be[col];
        X[idx] = fmaxf(v, 0.f);
    }
}

// ---------------- final matvec ----------------
__global__ void gemm5_kernel(const float* __restrict__ U4, const float* __restrict__ W5,
                             const float* __restrict__ b5, float* __restrict__ out)
{
    int warp = (blockIdx.x * blockDim.x + threadIdx.x) >> 5;
    int lane = threadIdx.x & 31;
    if (warp >= 8192) return;
    float s = U4[(size_t)warp * 64 + lane] * W5[lane]
            + U4[(size_t)warp * 64 + 32 + lane] * W5[32 + lane];
#pragma unroll
    for (int o = 16; o; o >>= 1) s += __shfl_xor_sync(0xffffffffu, s, o);
    if (lane == 0) out[warp] = s + b5[0];
}

// ---------------- launcher ----------------
extern "C" void kernel_launch(void* const* d_in, const int* in_sizes, int n_in,
                              void* d_out, int out_size)
{
    const float* lufeat = (const float*)d_in[0];
    const int*   llabel = (const int*)  d_in[1];
    const float* W1 = (const float*)d_in[2];
    const float* b1 = (const float*)d_in[3];
    const float* W2 = (const float*)d_in[4];
    const float* b2 = (const float*)d_in[5];
    const float* W3 = (const float*)d_in[6];
    const float* b3 = (const float*)d_in[7];
    const float* W4 = (const float*)d_in[8];
    const float* b4 = (const float*)d_in[9];
    const float* W5 = (const float*)d_in[10];
    const float* b5 = (const float*)d_in[11];
    const float* g1 = (const float*)d_in[12];
    const float* be1 = (const float*)d_in[13];
    const float* g2 = (const float*)d_in[14];
    const float* be2 = (const float*)d_in[15];
    const float* mbank0 = (const float*)d_in[16];
    const float* start0 = (const float*)d_in[17];
    float* out = (float*)d_out;

    float *H1, *H, *MB, *UF, *Y3, *Y4, *PS, *PQ, *MEAN, *INV;
    int *OCC, *CNT;
    __nv_bfloat16 *W1h, *W1l, *W2h, *W2l, *W3h, *W3l, *W4h, *W4l;
    cudaGetSymbolAddress((void**)&H1, g_H1);
    cudaGetSymbolAddress((void**)&H,  g_H);
    cudaGetSymbolAddress((void**)&MB, g_MB);
    cudaGetSymbolAddress((void**)&UF, g_UF);
    cudaGetSymbolAddress((void**)&Y3, g_Y3);
    cudaGetSymbolAddress((void**)&Y4, g_Y4);
    cudaGetSymbolAddress((void**)&PS, g_PS);
    cudaGetSymbolAddress((void**)&PQ, g_PQ);
    cudaGetSymbolAddress((void**)&MEAN, g_MEAN);
    cudaGetSymbolAddress((void**)&INV,  g_INV);
    cudaGetSymbolAddress((void**)&OCC, g_OCC);
    cudaGetSymbolAddress((void**)&CNT, g_CNT);
    cudaGetSymbolAddress((void**)&W1h, g_W1h); cudaGetSymbolAddress((void**)&W1l, g_W1l);
    cudaGetSymbolAddress((void**)&W2h, g_W2h); cudaGetSymbolAddress((void**)&W2l, g_W2l);
    cudaGetSymbolAddress((void**)&W3h, g_W3h); cudaGetSymbolAddress((void**)&W3l, g_W3l);
    cudaGetSymbolAddress((void**)&W4h, g_W4h); cudaGetSymbolAddress((void**)&W4l, g_W4l);

    const int SMEM_BYTES = 81920;
    // Unconditional (deterministic, idempotent): no static guards allowed.
    cudaFuncSetAttribute(mma_gemm, cudaFuncAttributeMaxDynamicSharedMemorySize, SMEM_BYTES);

    // weight splits (transposed), fused into one kernel
    split_all_kernel<<<3008, 256>>>(W1, W2, W3, W4,
                                    W1h, W1l, W2h, W2l, W3h, W3l, W4h, W4l);
    rank_kernel<<<40, 32>>>(llabel, OCC, CNT);

    // h = (lufeat @ W1 + b1) @ W2 + b2 ; normalize rows
    mma_gemm<<<dim3(4, 128), 256, SMEM_BYTES>>>(lufeat, 1024, W1h, W1l, b1, H1, 512, 1024);
    mma_gemm<<<dim3(2, 128), 256, SMEM_BYTES>>>(H1, 512, W2h, W2l, b2, H, 256, 512);
    norm_rows_kernel<<<2048, 256>>>(H);

    // memory bank EMA
    ema_kernel<<<40, 256>>>(H, OCC, CNT, mbank0, start0, MB, out + 16384);

    // distances
    dist_kernel<<<128, 256>>>(H, MB, out, UF);

    // layer 3: UF(8192x296, stride 320, zero-padded) @ W3 (Kp=320)
    mma_gemm<<<dim3(2, 64), 256, SMEM_BYTES>>>(UF, 320, W3h, W3l, b3, Y3, 256, 320);
    bn_part_kernel<<<64, 256>>>(Y3, 256, PS, PQ);
    bn_stats_kernel<<<1, 256>>>(PS, PQ, 256, MEAN, INV);
    bn_apply_kernel<<<(8192 * 256 + 255) / 256, 256>>>(Y3, 8192 * 256, 256, MEAN, INV, g1, be1);

    // layer 4: Y3(8192x256) @ W4 (N pad 128, Kp=256)
    mma_gemm<<<dim3(1, 64), 256, SMEM_BYTES>>>(Y3, 256, W4h, W4l, b4, Y4, 64, 256);
    bn_part_kernel<<<64, 64>>>(Y4, 64, PS, PQ);
    bn_stats_kernel<<<1, 64>>>(PS, PQ, 64, MEAN, INV);
    bn_apply_kernel<<<(8192 * 64 + 255) / 256, 256>>>(Y4, 8192 * 64, 64, MEAN, INV, g2, be2);

    // uscores
    gemm5_kernel<<<1024, 256>>>(Y4, W5, b5, out + 8192);
}

// round 14
// speedup vs baseline: 3.5539x; 1.0037x over previous
#include <cuda_runtime.h>
#include <cuda_bf16.h>
#include <cstdint>
#include <math.h>

// ---------------- scratch (device globals; no allocation allowed) ----------------
__device__ float g_H1[16384 * 512];   // lufeat@W1+b1
__device__ float g_H [16384 * 256];   // (..)@W2+b2, then normalized in place
__device__ float g_MB[40 * 256];      // memory bank after scan
__device__ float g_UF[8192 * 320];    // concat(ufeat, um), padded 296->320
__device__ float g_Y3[8192 * 256];
__device__ float g_Y4[8192 * 64];
__device__ float g_PS[64 * 256];
__device__ float g_PQ[64 * 256];
__device__ float g_MEAN[256];
__device__ float g_INV[256];
__device__ int   g_OCC[40 * 8192];
__device__ int   g_CNT[40];
// bf16 hi/lo split weights, TRANSPOSED layout: W^T[n][k], row stride = Kp
__device__ __align__(16) __nv_bfloat16 g_W1h[512 * 1024], g_W1l[512 * 1024];
__device__ __align__(16) __nv_bfloat16 g_W2h[256 * 512],  g_W2l[256 * 512];
__device__ __align__(16) __nv_bfloat16 g_W3h[256 * 320],  g_W3l[256 * 320];   // K pad 296->320
__device__ __align__(16) __nv_bfloat16 g_W4h[128 * 256],  g_W4l[128 * 256];   // N pad 64->128

// ---------------- fused: split all weights into transposed bf16 hi/lo ----------------
__global__ void split_all_kernel(
    const float* __restrict__ W1, const float* __restrict__ W2,
    const float* __restrict__ W3, const float* __restrict__ W4,
    __nv_bfloat16* __restrict__ W1h, __nv_bfloat16* __restrict__ W1l,
    __nv_bfloat16* __restrict__ W2h, __nv_bfloat16* __restrict__ W2l,
    __nv_bfloat16* __restrict__ W3h, __nv_bfloat16* __restrict__ W3l,
    __nv_bfloat16* __restrict__ W4h, __nv_bfloat16* __restrict__ W4l)
{
    int b = blockIdx.x;
    const float* W; __nv_bfloat16 *Wh, *Wl; int K, N, Kp, idx0;
    if (b < 2048)      { W = W1; Wh = W1h; Wl = W1l; K = 1024; N = 512; Kp = 1024; idx0 = b * 256; }
    else if (b < 2560) { W = W2; Wh = W2h; Wl = W2l; K = 512;  N = 256; Kp = 512;  idx0 = (b - 2048) * 256; }
    else if (b < 2880) { W = W3; Wh = W3h; Wl = W3l; K = 296;  N = 256; Kp = 320;  idx0 = (b - 2560) * 256; }
    else               { W = W4; Wh = W4h; Wl = W4l; K = 256;  N = 64;  Kp = 256;  idx0 = (b - 2880) * 256; }
    int idx = idx0 + threadIdx.x;
    int n = idx / Kp, k = idx - n * Kp;
    float v = (k < K && n < N) ? W[k * N + n] : 0.f;
    __nv_bfloat16 h = __float2bfloat16(v);
    float r = v - __bfloat162float(h);
    Wh[idx] = h;
    Wl[idx] = __float2bfloat16(r);
}

// ---------------- ldmatrix helpers ----------------
__device__ __forceinline__ void ldsm_x4(unsigned int* r, const void* p) {
    unsigned int addr = (unsigned int)__cvta_generic_to_shared(p);
    asm volatile("ldmatrix.sync.aligned.m8n8.x4.shared.b16 {%0,%1,%2,%3}, [%4];"
        : "=r"(r[0]), "=r"(r[1]), "=r"(r[2]), "=r"(r[3]) : "r"(addr));
}

// ---------------- bf16-split tensor-core GEMM: C = A(f32) @ B + bias ------------------
// B given TRANSPOSED (B^T[n][k], row stride Kp). BM=128, BN=128, BK=32.
// 256 threads = 8 warps (4x2), each warp 32x64. Double-buffered smem + cp.async + ldmatrix.
__global__ __launch_bounds__(256, 2) void mma_gemm(
    const float* __restrict__ A, int lda,
    const __nv_bfloat16* __restrict__ BhT, const __nv_bfloat16* __restrict__ BlT,
    const float* __restrict__ bias, float* __restrict__ C,
    int N, int Kp)
{
    extern __shared__ __nv_bfloat16 sm[];
    __nv_bfloat16* sAh = sm;            // [2][128][40]
    __nv_bfloat16* sAl = sm + 10240;
    __nv_bfloat16* sBh = sm + 20480;    // [2][128 n][40 k]
    __nv_bfloat16* sBl = sm + 30720;

    const int tid = threadIdx.x;
    const int lane = tid & 31, warp = tid >> 5;
    const int g = lane >> 2, tig = lane & 3;
    const int warpM = (warp >> 1) * 32;
    const int warpN = (warp & 1) * 64;
    const int bm = blockIdx.y * 128;
    const int bn = blockIdx.x * 128;

    // ldmatrix lane-address components
    const int lm_row = lane & 15;            // row within 16-row tile pair
    const int lm_koff = (lane >> 4) * 8;     // k offset 0 or 8

    float acc[2][8][4];
#pragma unroll
    for (int i = 0; i < 2; i++)
#pragma unroll
        for (int j = 0; j < 8; j++)
#pragma unroll
            for (int q = 0; q < 4; q++) acc[i][j][q] = 0.f;

    const int nk = Kp / 32;
    float4 ra[4];

    // A: v = tid + 256*i -> row = v>>3, col = (v&7)*4
    auto loadA = [&](int k0) {
#pragma unroll
        for (int i = 0; i < 4; i++) {
            int v = tid + 256 * i;
            int r = v >> 3, c = (v & 7) * 4;
            ra[i] = *(const float4*)(A + (size_t)(bm + r) * lda + k0 + c);
        }
    };
    auto storeA = [&](int buf) {
        __nv_bfloat16* dh = sAh + buf * 5120;
        __nv_bfloat16* dl = sAl + buf * 5120;
#pragma unroll
        for (int i = 0; i < 4; i++) {
            int v = tid + 256 * i;
            int r = v >> 3, c = (v & 7) * 4;
            float f[4] = { ra[i].x, ra[i].y, ra[i].z, ra[i].w };
            __nv_bfloat16 h[4], l[4];
#pragma unroll
            for (int q = 0; q < 4; q++) {
                h[q] = __float2bfloat16(f[q]);
                l[q] = __float2bfloat16(f[q] - __bfloat162float(h[q]));
            }
            __nv_bfloat162 hh0; hh0.x = h[0]; hh0.y = h[1];
            __nv_bfloat162 hh1; hh1.x = h[2]; hh1.y = h[3];
            __nv_bfloat162 ll0; ll0.x = l[0]; ll0.y = l[1];
            __nv_bfloat162 ll1; ll1.x = l[2]; ll1.y = l[3];
            *(__nv_bfloat162*)&dh[r * 40 + c]     = hh0;
            *(__nv_bfloat162*)&dh[r * 40 + c + 2] = hh1;
            *(__nv_bfloat162*)&dl[r * 40 + c]     = ll0;
            *(__nv_bfloat162*)&dl[r * 40 + c + 2] = ll1;
        }
    };
    // B: v = tid + 256*i -> n = v>>2, kc = (v&3)*8 ; 16B cp.async each, hi+lo
    auto cpB = [&](int k0, int buf) {
#pragma unroll
        for (int i = 0; i < 2; i++) {
            int v = tid + 256 * i;
            int n = v >> 2, kc = (v & 3) * 8;
            const __nv_bfloat16* gh = BhT + (size_t)(bn + n) * Kp + k0 + kc;
            const __nv_bfloat16* gl = BlT + (size_t)(bn + n) * Kp + k0 + kc;
            unsigned dsth = (unsigned)__cvta_generic_to_shared(&sBh[buf * 5120 + n * 40 + kc]);
            unsigned dstl = (unsigned)__cvta_generic_to_shared(&sBl[buf * 5120 + n * 40 + kc]);
            asm volatile("cp.async.ca.shared.global [%0], [%1], 16;" :: "r"(dsth), "l"(gh));
            asm volatile("cp.async.ca.shared.global [%0], [%1], 16;" :: "r"(dstl), "l"(gl));
        }
        asm volatile("cp.async.commit_group;");
    };

    // prologue
    loadA(0);
    cpB(0, 0);
    storeA(0);
    asm volatile("cp.async.wait_group 0;");
    __syncthreads();

    for (int t = 0; t < nk; t++) {
        int cur = t & 1, nxt = cur ^ 1;
        bool more = (t + 1 < nk);
        if (more) {
            loadA((t + 1) * 32);
            cpB((t + 1) * 32, nxt);
        }

        const __nv_bfloat16* pAh = sAh + cur * 5120;
        const __nv_bfloat16* pAl = sAl + cur * 5120;
        const __nv_bfloat16* pBh = sBh + cur * 5120;
        const __nv_bfloat16* pBl = sBl + cur * 5120;

#pragma unroll
        for (int kk = 0; kk < 32; kk += 16) {
            // A fragments via ldmatrix.x4: rows (warpM+i*16+lm_row), col kk+lm_koff
            unsigned int ah[2][4], al[2][4];
#pragma unroll
            for (int i = 0; i < 2; i++) {
                const __nv_bfloat16* pa = pAh + (warpM + i * 16 + lm_row) * 40 + kk + lm_koff;
                ldsm_x4(ah[i], pa);
                const __nv_bfloat16* pl = pAl + (warpM + i * 16 + lm_row) * 40 + kk + lm_koff;
                ldsm_x4(al[i], pl);
            }
            // B fragments: 4 groups of 2 j's; x4 gives {j0 b0, j1 b0, j0 b1, j1 b1}
#pragma unroll
            for (int jj = 0; jj < 4; jj++) {
                unsigned int bh[4], bl[4];
                const __nv_bfloat16* pb = pBh + (warpN + jj * 16 + lm_row) * 40 + kk + lm_koff;
                ldsm_x4(bh, pb);
                const __nv_bfloat16* pbl2 = pBl + (warpN + jj * 16 + lm_row) * 40 + kk + lm_koff;
                ldsm_x4(bl, pbl2);
#pragma unroll
                for (int odd = 0; odd < 2; odd++) {
                    int j = jj * 2 + odd;
                    unsigned int bh0 = bh[odd], bh1 = bh[odd + 2];
                    unsigned int bl0 = bl[odd], bl1 = bl[odd + 2];
#pragma unroll
                    for (int i = 0; i < 2; i++) {
                        float* d = acc[i][j];
                        asm volatile(
                            "mma.sync.aligned.m16n8k16.row.col.f32.bf16.bf16.f32 "
                            "{%0,%1,%2,%3}, {%4,%5,%6,%7}, {%8,%9}, {%0,%1,%2,%3};"
                            : "+f"(d[0]), "+f"(d[1]), "+f"(d[2]), "+f"(d[3])
                            : "r"(ah[i][0]), "r"(ah[i][1]), "r"(ah[i][2]), "r"(ah[i][3]),
                              "r"(bh0), "r"(bh1));
                        asm volatile(
                            "mma.sync.aligned.m16n8k16.row.col.f32.bf16.bf16.f32 "
                            "{%0,%1,%2,%3}, {%4,%5,%6,%7}, {%8,%9}, {%0,%1,%2,%3};"
                            : "+f"(d[0]), "+f"(d[1]), "+f"(d[2]), "+f"(d[3])
                            : "r"(ah[i][0]), "r"(ah[i][1]), "r"(ah[i][2]), "r"(ah[i][3]),
                              "r"(bl0), "r"(bl1));
                        asm volatile(
                            "mma.sync.aligned.m16n8k16.row.col.f32.bf16.bf16.f32 "
                            "{%0,%1,%2,%3}, {%4,%5,%6,%7}, {%8,%9}, {%0,%1,%2,%3};"
                            : "+f"(d[0]), "+f"(d[1]), "+f"(d[2]), "+f"(d[3])
                            : "r"(al[i][0]), "r"(al[i][1]), "r"(al[i][2]), "r"(al[i][3]),
                              "r"(bh0), "r"(bh1));
                    }
                }
            }
        }

        if (more) {
            storeA(nxt);
            asm volatile("cp.async.wait_group 0;");
        }
        __syncthreads();
    }

    // epilogue
#pragma unroll
    for (int i = 0; i < 2; i++) {
        int r = bm + warpM + i * 16 + g;
#pragma unroll
        for (int j = 0; j < 8; j++) {
            int c = bn + warpN + j * 8 + tig * 2;
            if (c < N) {
                float2 v0 = make_float2(acc[i][j][0] + bias[c], acc[i][j][1] + bias[c + 1]);
                float2 v1 = make_float2(acc[i][j][2] + bias[c], acc[i][j][3] + bias[c + 1]);
                *(float2*)(C + (size_t)r * N + c) = v0;
                *(float2*)(C + (size_t)(r + 8) * N + c) = v1;
            }
        }
    }
}

// ---------------- row L2-normalize H (16384 x 256), one warp per row ----------------
__global__ void norm_rows_kernel(float* __restrict__ H)
{
    int warp = (blockIdx.x * blockDim.x + threadIdx.x) >> 5;
    int lane = threadIdx.x & 31;
    if (warp >= 16384) return;
    float* rowp = H + (size_t)warp * 256;
    float4 a = *(const float4*)(rowp + lane * 4);
    float4 b = *(const float4*)(rowp + 128 + lane * 4);
    float s = a.x * a.x + a.y * a.y + a.z * a.z + a.w * a.w
            + b.x * b.x + b.y * b.y + b.z * b.z + b.w * b.w;
#pragma unroll
    for (int o = 16; o; o >>= 1) s += __shfl_xor_sync(0xffffffffu, s, o);
    float inv = 1.0f / sqrtf(s);
    a.x *= inv; a.y *= inv; a.z *= inv; a.w *= inv;
    b.x *= inv; b.y *= inv; b.z *= inv; b.w *= inv;
    *(float4*)(rowp + lane * 4) = a;
    *(float4*)(rowp + 128 + lane * 4) = b;
}

// ---------------- scan phase 1: per-class ordered occurrence lists ----------------
__global__ void rank_kernel(const int* __restrict__ llabel,
                            int* __restrict__ occ, int* __restrict__ cnt)
{
    int c = blockIdx.x;
    int lane = threadIdx.x;
    int base = 0;
    for (int i0 = 0; i0 < 8192; i0 += 32) {
        int lab = llabel[i0 + lane];
        unsigned m = __ballot_sync(0xffffffffu, lab == c);
        if (lab == c) {
            int r = base + __popc(m & ((1u << lane) - 1u));
            occ[c * 8192 + r] = i0 + lane;
        }
        base += __popc(m);
    }
    if (lane == 0) cnt[c] = base;
}

// ---------------- scan phase 2: EMA over each class's occurrences ----------------
__global__ void ema_kernel(const float* __restrict__ H,
                           const int* __restrict__ occ, const int* __restrict__ cnt,
                           const float* __restrict__ mbank0, const float* __restrict__ start0,
                           float* __restrict__ MB, float* __restrict__ out_mbank)
{
    int c = blockIdx.x;
    int d = threadIdx.x;
    __shared__ int idxs[256];
    int n = cnt[c];
    float row = mbank0[c * 256 + d];
    bool started = (start0[c] != 0.0f);
    for (int r0 = 0; r0 < n; r0 += 256) {
        __syncthreads();
        if (r0 + d < n) idxs[d] = occ[c * 8192 + r0 + d];
        __syncthreads();
        int lim = min(256, n - r0);
#pragma unroll 4
        for (int j = 0; j < lim; j++) {
            float f = H[(size_t)idxs[j] * 256 + d];
            row = started ? fmaf(0.9f, row, 0.1f * f) : f;
            started = true;
        }
    }
    MB[c * 256 + d] = row;
    out_mbank[c * 256 + d] = row;
}

// ---------------- distances: lscores for labeled, UF = [ufeat | um | 0pad] ----------------
__global__ void dist_kernel(const float* __restrict__ H, const float* __restrict__ MB,
                            float* __restrict__ lscores, float* __restrict__ UF)
{
    __shared__ float mb[40 * 256];
    for (int i = threadIdx.x; i < 40 * 256; i += blockDim.x) mb[i] = MB[i];
    __syncthreads();

    int nwarp = (gridDim.x * blockDim.x) >> 5;
    int warp = (blockIdx.x * blockDim.x + threadIdx.x) >> 5;
    int lane = threadIdx.x & 31;

    for (int row = warp; row < 16384; row += nwarp) {
        float h[8];
#pragma unroll
        for (int k = 0; k < 8; k++) h[k] = H[(size_t)row * 256 + lane + 32 * k];
        if (row < 8192) {
            float best = 3.4e38f;
            for (int c = 0; c < 40; c++) {
                float s = 0.f;
#pragma unroll
                for (int k = 0; k < 8; k++) {
                    float dl = h[k] - mb[c * 256 + lane + 32 * k];
                    s = fmaf(dl, dl, s);
                }
#pragma unroll
                for (int o = 16; o; o >>= 1) s += __shfl_xor_sync(0xffffffffu, s, o);
                best = fminf(best, s);
            }
            if (lane == 0) lscores[row] = sqrtf(best);
        } else {
            int r = row - 8192;
#pragma unroll
            for (int k = 0; k < 8; k++)
                UF[(size_t)r * 320 + lane + 32 * k] = h[k];
            for (int c = 0; c < 40; c++) {
                float s = 0.f;
#pragma unroll
                for (int k = 0; k < 8; k++) {
                    float dl = h[k] - mb[c * 256 + lane + 32 * k];
                    s = fmaf(dl, dl, s);
                }
#pragma unroll
                for (int o = 16; o; o >>= 1) s += __shfl_xor_sync(0xffffffffu, s, o);
                if (lane == 0) UF[(size_t)r * 320 + 256 + c] = sqrtf(s);
            }
            if (lane < 24) UF[(size_t)r * 320 + 296 + lane] = 0.f;  // zero pad 296..319
        }
    }
}

// ---------------- BN stage 1: per-block partial column sums (deterministic) ----------------
__global__ void bn_part_kernel(const float* __restrict__ X, int cols,
                               float* __restrict__ ps, float* __restrict__ pq)
{
    int col = threadIdx.x;
    int r0 = blockIdx.x * 128;
    float s = 0.f, q = 0.f;
    for (int r = r0; r < r0 + 128; r++) {
        float v = X[(size_t)r * cols + col];
        s += v;
        q = fmaf(v, v, q);
    }
    ps[blockIdx.x * cols + col] = s;
    pq[blockIdx.x * cols + col] = q;
}

// ---------------- BN stage 2: fold 64 partials ----------------
__global__ void bn_stats_kernel(const float* __restrict__ ps, const float* __restrict__ pq,
                                int cols, float* __restrict__ mean, float* __restrict__ inv)
{
    int col = threadIdx.x;
    float s = 0.f, q = 0.f;
    for (int b = 0; b < 64; b++) { s += ps[b * cols + col]; q += pq[b * cols + col]; }
    float mu = s * (1.0f / 8192.0f);
    float var = q * (1.0f / 8192.0f) - mu * mu;
    mean[col] = mu;
    inv[col] = 1.0f / sqrtf(var + 1e-5f);
}

// ---------------- BN apply + ReLU (in place) ----------------
__global__ void bn_apply_kernel(float* __restrict__ X, int n, int cols,
                                const float* __restrict__ mean, const float* __restrict__ inv,
                                const float* __restrict__ g, const float* __restrict__ be)
{
    int idx = blockIdx.x * blockDim.x + threadIdx.x;
    if (idx < n) {
        int col = idx & (cols - 1);
        float v = (X[idx] - mean[col]) * inv[col] * g[col] + be[col];
        X[idx] = fmaxf(v, 0.f);
    }
}

// ---------------- final matvec ----------------
__global__ void gemm5_kernel(const float* __restrict__ U4, const float* __restrict__ W5,
                             const float* __restrict__ b5, float* __restrict__ out)
{
    int warp = (blockIdx.x * blockDim.x + threadIdx.x) >> 5;
    int lane = threadIdx.x & 31;
    if (warp >= 8192) return;
    float s = U4[(size_t)warp * 64 + lane] * W5[lane]
            + U4[(size_t)warp * 64 + 32 + lane] * W5[32 + lane];
#pragma unroll
    for (int o = 16; o; o >>= 1) s += __shfl_xor_sync(0xffffffffu, s, o);
    if (lane == 0) out[warp] = s + b5[0];
}

// ---------------- launcher ----------------
extern "C" void kernel_launch(void* const* d_in, const int* in_sizes, int n_in,
                              void* d_out, int out_size)
{
    const float* lufeat = (const float*)d_in[0];
    const int*   llabel = (const int*)  d_in[1];
    const float* W1 = (const float*)d_in[2];
    const float* b1 = (const float*)d_in[3];
    const float* W2 = (const float*)d_in[4];
    const float* b2 = (const float*)d_in[5];
    const float* W3 = (const float*)d_in[6];
    const float* b3 = (const float*)d_in[7];
    const float* W4 = (const float*)d_in[8];
    const float* b4 = (const float*)d_in[9];
    const float* W5 = (const float*)d_in[10];
    const float* b5 = (const float*)d_in[11];
    const float* g1 = (const float*)d_in[12];
    const float* be1 = (const float*)d_in[13];
    const float* g2 = (const float*)d_in[14];
    const float* be2 = (const float*)d_in[15];
    const float* mbank0 = (const float*)d_in[16];
    const float* start0 = (const float*)d_in[17];
    float* out = (float*)d_out;

    float *H1, *H, *MB, *UF, *Y3, *Y4, *PS, *PQ, *MEAN, *INV;
    int *OCC, *CNT;
    __nv_bfloat16 *W1h, *W1l, *W2h, *W2l, *W3h, *W3l, *W4h, *W4l;
    cudaGetSymbolAddress((void**)&H1, g_H1);
    cudaGetSymbolAddress((void**)&H,  g_H);
    cudaGetSymbolAddress((void**)&MB, g_MB);
    cudaGetSymbolAddress((void**)&UF, g_UF);
    cudaGetSymbolAddress((void**)&Y3, g_Y3);
    cudaGetSymbolAddress((void**)&Y4, g_Y4);
    cudaGetSymbolAddress((void**)&PS, g_PS);
    cudaGetSymbolAddress((void**)&PQ, g_PQ);
    cudaGetSymbolAddress((void**)&MEAN, g_MEAN);
    cudaGetSymbolAddress((void**)&INV,  g_INV);
    cudaGetSymbolAddress((void**)&OCC, g_OCC);
    cudaGetSymbolAddress((void**)&CNT, g_CNT);
    cudaGetSymbolAddress((void**)&W1h, g_W1h); cudaGetSymbolAddress((void**)&W1l, g_W1l);
    cudaGetSymbolAddress((void**)&W2h, g_W2h); cudaGetSymbolAddress((void**)&W2l, g_W2l);
    cudaGetSymbolAddress((void**)&W3h, g_W3h); cudaGetSymbolAddress((void**)&W3l, g_W3l);
    cudaGetSymbolAddress((void**)&W4h, g_W4h); cudaGetSymbolAddress((void**)&W4l, g_W4l);

    const int SMEM_BYTES = 81920;
    cudaFuncSetAttribute(mma_gemm, cudaFuncAttributeMaxDynamicSharedMemorySize, SMEM_BYTES);

    // weight splits (transposed), fused into one kernel
    split_all_kernel<<<3008, 256>>>(W1, W2, W3, W4,
                                    W1h, W1l, W2h, W2l, W3h, W3l, W4h, W4l);
    rank_kernel<<<40, 32>>>(llabel, OCC, CNT);

    // h = (lufeat @ W1 + b1) @ W2 + b2 ; normalize rows
    mma_gemm<<<dim3(4, 128), 256, SMEM_BYTES>>>(lufeat, 1024, W1h, W1l, b1, H1, 512, 1024);
    mma_gemm<<<dim3(2, 128), 256, SMEM_BYTES>>>(H1, 512, W2h, W2l, b2, H, 256, 512);
    norm_rows_kernel<<<2048, 256>>>(H);

    // memory bank EMA
    ema_kernel<<<40, 256>>>(H, OCC, CNT, mbank0, start0, MB, out + 16384);

    // distances
    dist_kernel<<<128, 256>>>(H, MB, out, UF);

    // layer 3: UF(8192x296, stride 320, zero-padded) @ W3 (Kp=320)
    mma_gemm<<<dim3(2, 64), 256, SMEM_BYTES>>>(UF, 320, W3h, W3l, b3, Y3, 256, 320);
    bn_part_kernel<<<64, 256>>>(Y3, 256, PS, PQ);
    bn_stats_kernel<<<1, 256>>>(PS, PQ, 256, MEAN, INV);
    bn_apply_kernel<<<(8192 * 256 + 255) / 256, 256>>>(Y3, 8192 * 256, 256, MEAN, INV, g1, be1);

    // layer 4: Y3(8192x256) @ W4 (N pad 128, Kp=256)
    mma_gemm<<<dim3(1, 64), 256, SMEM_BYTES>>>(Y3, 256, W4h, W4l, b4, Y4, 64, 256);
    bn_part_kernel<<<64, 64>>>(Y4, 64, PS, PQ);
    bn_stats_kernel<<<1, 64>>>(PS, PQ, 64, MEAN, INV);
    bn_apply_kernel<<<(8192 * 64 + 255) / 256, 256>>>(Y4, 8192 * 64, 64, MEAN, INV, g2, be2);

    // uscores
    gemm5_kernel<<<1024, 256>>>(Y4, W5, b5, out + 8192);
}

// round 16
// speedup vs baseline: 4.4534x; 1.2531x over previous
#include <cuda_runtime.h>
#include <cuda_bf16.h>
#include <cstdint>
#include <math.h>

// ---------------- scratch (device globals; no allocation allowed) ----------------
__device__ float g_H [16384 * 256];   // X@W12+b12, then normalized in place
__device__ float g_MB[40 * 256];      // memory bank after scan
__device__ float g_UF[8192 * 320];    // concat(ufeat, um), padded 296->320
__device__ float g_Y3[8192 * 256];
__device__ float g_Y4[8192 * 64];
__device__ float g_PS[64 * 256];
__device__ float g_PQ[64 * 256];
__device__ float g_MEAN[256];
__device__ float g_INV[256];
__device__ int   g_OCC[40 * 8192];
__device__ int   g_CNT[40];
__device__ float g_W12[1024 * 256];   // W1@W2 (f32)
__device__ float g_B12[256];          // b1@W2 + b2
__device__ float g_ZERO[256];         // static zero bias (never written)
// bf16 hi/lo split weights, TRANSPOSED layout: W^T[n][k], row stride = Kp
__device__ __align__(16) __nv_bfloat16 g_W2h[256 * 512],   g_W2l[256 * 512];
__device__ __align__(16) __nv_bfloat16 g_W3h[256 * 320],   g_W3l[256 * 320];   // K pad 296->320
__device__ __align__(16) __nv_bfloat16 g_W4h[128 * 256],   g_W4l[128 * 256];   // N pad 64->128
__device__ __align__(16) __nv_bfloat16 g_W12h[256 * 1024], g_W12l[256 * 1024]; // [256 n][1024 k]

// ---------------- fused: split W2/W3/W4 into transposed bf16 hi/lo ----------------
__global__ void split_all_kernel(
    const float* __restrict__ W2, const float* __restrict__ W3, const float* __restrict__ W4,
    __nv_bfloat16* __restrict__ W2h, __nv_bfloat16* __restrict__ W2l,
    __nv_bfloat16* __restrict__ W3h, __nv_bfloat16* __restrict__ W3l,
    __nv_bfloat16* __restrict__ W4h, __nv_bfloat16* __restrict__ W4l)
{
    int b = blockIdx.x;
    const float* W; __nv_bfloat16 *Wh, *Wl; int K, N, Kp, idx0;
    if (b < 512)      { W = W2; Wh = W2h; Wl = W2l; K = 512; N = 256; Kp = 512; idx0 = b * 256; }
    else if (b < 832) { W = W3; Wh = W3h; Wl = W3l; K = 296; N = 256; Kp = 320; idx0 = (b - 512) * 256; }
    else              { W = W4; Wh = W4h; Wl = W4l; K = 256; N = 64;  Kp = 256; idx0 = (b - 832) * 256; }
    int idx = idx0 + threadIdx.x;
    int n = idx / Kp, k = idx - n * Kp;
    float v = (k < K && n < N) ? W[k * N + n] : 0.f;
    __nv_bfloat16 h = __float2bfloat16(v);
    float r = v - __bfloat162float(h);
    Wh[idx] = h;
    Wl[idx] = __float2bfloat16(r);
}

// ---------------- split W12 (f32 [1024 k][256 n]) -> transposed bf16 hi/lo ----------
__global__ void split_w12_kernel(const float* __restrict__ W12,
                                 __nv_bfloat16* __restrict__ Wh, __nv_bfloat16* __restrict__ Wl)
{
    int idx = blockIdx.x * 256 + threadIdx.x;     // over 256*1024
    int n = idx >> 10, k = idx & 1023;
    float v = W12[k * 256 + n];
    __nv_bfloat16 h = __float2bfloat16(v);
    float r = v - __bfloat162float(h);
    Wh[idx] = h;
    Wl[idx] = __float2bfloat16(r);
}

// ---------------- b12 = b1 @ W2 + b2 ----------------
__global__ void bias12_kernel(const float* __restrict__ b1, const float* __restrict__ W2,
                              const float* __restrict__ b2, float* __restrict__ B12)
{
    int n = threadIdx.x;   // 256
    float s = b2[n];
    for (int k = 0; k < 512; k++) s = fmaf(b1[k], W2[k * 256 + n], s);
    B12[n] = s;
}

// ---------------- ldmatrix helpers ----------------
__device__ __forceinline__ void ldsm_x4(unsigned int* r, const void* p) {
    unsigned int addr = (unsigned int)__cvta_generic_to_shared(p);
    asm volatile("ldmatrix.sync.aligned.m8n8.x4.shared.b16 {%0,%1,%2,%3}, [%4];"
        : "=r"(r[0]), "=r"(r[1]), "=r"(r[2]), "=r"(r[3]) : "r"(addr));
}

// ---------------- bf16-split tensor-core GEMM: C = A(f32) @ B + bias ------------------
// B given TRANSPOSED (B^T[n][k], row stride Kp). BM=128, BN=128, BK=32.
// 256 threads = 8 warps (4x2), each warp 32x64. Double-buffered smem + cp.async + ldmatrix.
__global__ __launch_bounds__(256, 2) void mma_gemm(
    const float* __restrict__ A, int lda,
    const __nv_bfloat16* __restrict__ BhT, const __nv_bfloat16* __restrict__ BlT,
    const float* __restrict__ bias, float* __restrict__ C,
    int N, int Kp)
{
    extern __shared__ __nv_bfloat16 sm[];
    __nv_bfloat16* sAh = sm;            // [2][128][40]
    __nv_bfloat16* sAl = sm + 10240;
    __nv_bfloat16* sBh = sm + 20480;    // [2][128 n][40 k]
    __nv_bfloat16* sBl = sm + 30720;

    const int tid = threadIdx.x;
    const int lane = tid & 31, warp = tid >> 5;
    const int g = lane >> 2, tig = lane & 3;
    const int warpM = (warp >> 1) * 32;
    const int warpN = (warp & 1) * 64;
    const int bm = blockIdx.y * 128;
    const int bn = blockIdx.x * 128;

    const int lm_row = lane & 15;
    const int lm_koff = (lane >> 4) * 8;

    float acc[2][8][4];
#pragma unroll
    for (int i = 0; i < 2; i++)
#pragma unroll
        for (int j = 0; j < 8; j++)
#pragma unroll
            for (int q = 0; q < 4; q++) acc[i][j][q] = 0.f;

    const int nk = Kp / 32;
    float4 ra[4];

    auto loadA = [&](int k0) {
#pragma unroll
        for (int i = 0; i < 4; i++) {
            int v = tid + 256 * i;
            int r = v >> 3, c = (v & 7) * 4;
            ra[i] = *(const float4*)(A + (size_t)(bm + r) * lda + k0 + c);
        }
    };
    auto storeA = [&](int buf) {
        __nv_bfloat16* dh = sAh + buf * 5120;
        __nv_bfloat16* dl = sAl + buf * 5120;
#pragma unroll
        for (int i = 0; i < 4; i++) {
            int v = tid + 256 * i;
            int r = v >> 3, c = (v & 7) * 4;
            float f[4] = { ra[i].x, ra[i].y, ra[i].z, ra[i].w };
            __nv_bfloat16 h[4], l[4];
#pragma unroll
            for (int q = 0; q < 4; q++) {
                h[q] = __float2bfloat16(f[q]);
                l[q] = __float2bfloat16(f[q] - __bfloat162float(h[q]));
            }
            __nv_bfloat162 hh0; hh0.x = h[0]; hh0.y = h[1];
            __nv_bfloat162 hh1; hh1.x = h[2]; hh1.y = h[3];
            __nv_bfloat162 ll0; ll0.x = l[0]; ll0.y = l[1];
            __nv_bfloat162 ll1; ll1.x = l[2]; ll1.y = l[3];
            *(__nv_bfloat162*)&dh[r * 40 + c]     = hh0;
            *(__nv_bfloat162*)&dh[r * 40 + c + 2] = hh1;
            *(__nv_bfloat162*)&dl[r * 40 + c]     = ll0;
            *(__nv_bfloat162*)&dl[r * 40 + c + 2] = ll1;
        }
    };
    auto cpB = [&](int k0, int buf) {
#pragma unroll
        for (int i = 0; i < 2; i++) {
            int v = tid + 256 * i;
            int n = v >> 2, kc = (v & 3) * 8;
            const __nv_bfloat16* gh = BhT + (size_t)(bn + n) * Kp + k0 + kc;
            const __nv_bfloat16* gl = BlT + (size_t)(bn + n) * Kp + k0 + kc;
            unsigned dsth = (unsigned)__cvta_generic_to_shared(&sBh[buf * 5120 + n * 40 + kc]);
            unsigned dstl = (unsigned)__cvta_generic_to_shared(&sBl[buf * 5120 + n * 40 + kc]);
            asm volatile("cp.async.ca.shared.global [%0], [%1], 16;" :: "r"(dsth), "l"(gh));
            asm volatile("cp.async.ca.shared.global [%0], [%1], 16;" :: "r"(dstl), "l"(gl));
        }
        asm volatile("cp.async.commit_group;");
    };

    loadA(0);
    cpB(0, 0);
    storeA(0);
    asm volatile("cp.async.wait_group 0;");
    __syncthreads();

    for (int t = 0; t < nk; t++) {
        int cur = t & 1, nxt = cur ^ 1;
        bool more = (t + 1 < nk);
        if (more) {
            loadA((t + 1) * 32);
            cpB((t + 1) * 32, nxt);
        }

        const __nv_bfloat16* pAh = sAh + cur * 5120;
        const __nv_bfloat16* pAl = sAl + cur * 5120;
        const __nv_bfloat16* pBh = sBh + cur * 5120;
        const __nv_bfloat16* pBl = sBl + cur * 5120;

#pragma unroll
        for (int kk = 0; kk < 32; kk += 16) {
            unsigned int ah[2][4], al[2][4];
#pragma unroll
            for (int i = 0; i < 2; i++) {
                const __nv_bfloat16* pa = pAh + (warpM + i * 16 + lm_row) * 40 + kk + lm_koff;
                ldsm_x4(ah[i], pa);
                const __nv_bfloat16* pl = pAl + (warpM + i * 16 + lm_row) * 40 + kk + lm_koff;
                ldsm_x4(al[i], pl);
            }
#pragma unroll
            for (int jj = 0; jj < 4; jj++) {
                unsigned int bh[4], bl[4];
                const __nv_bfloat16* pb = pBh + (warpN + jj * 16 + lm_row) * 40 + kk + lm_koff;
                ldsm_x4(bh, pb);
                const __nv_bfloat16* pbl2 = pBl + (warpN + jj * 16 + lm_row) * 40 + kk + lm_koff;
                ldsm_x4(bl, pbl2);
#pragma unroll
                for (int odd = 0; odd < 2; odd++) {
                    int j = jj * 2 + odd;
                    unsigned int bh0 = bh[odd], bh1 = bh[odd + 2];
                    unsigned int bl0 = bl[odd], bl1 = bl[odd + 2];
#pragma unroll
                    for (int i = 0; i < 2; i++) {
                        float* d = acc[i][j];
                        asm volatile(
                            "mma.sync.aligned.m16n8k16.row.col.f32.bf16.bf16.f32 "
                            "{%0,%1,%2,%3}, {%4,%5,%6,%7}, {%8,%9}, {%0,%1,%2,%3};"
                            : "+f"(d[0]), "+f"(d[1]), "+f"(d[2]), "+f"(d[3])
                            : "r"(ah[i][0]), "r"(ah[i][1]), "r"(ah[i][2]), "r"(ah[i][3]),
                              "r"(bh0), "r"(bh1));
                        asm volatile(
                            "mma.sync.aligned.m16n8k16.row.col.f32.bf16.bf16.f32 "
                            "{%0,%1,%2,%3}, {%4,%5,%6,%7}, {%8,%9}, {%0,%1,%2,%3};"
                            : "+f"(d[0]), "+f"(d[1]), "+f"(d[2]), "+f"(d[3])
                            : "r"(ah[i][0]), "r"(ah[i][1]), "r"(ah[i][2]), "r"(ah[i][3]),
                              "r"(bl0), "r"(bl1));
                        asm volatile(
                            "mma.sync.aligned.m16n8k16.row.col.f32.bf16.bf16.f32 "
                            "{%0,%1,%2,%3}, {%4,%5,%6,%7}, {%8,%9}, {%0,%1,%2,%3};"
                            : "+f"(d[0]), "+f"(d[1]), "+f"(d[2]), "+f"(d[3])
                            : "r"(al[i][0]), "r"(al[i][1]), "r"(al[i][2]), "r"(al[i][3]),
                              "r"(bh0), "r"(bh1));
                    }
                }
            }
        }

        if (more) {
            storeA(nxt);
            asm volatile("cp.async.wait_group 0;");
        }
        __syncthreads();
    }

#pragma unroll
    for (int i = 0; i < 2; i++) {
        int r = bm + warpM + i * 16 + g;
#pragma unroll
        for (int j = 0; j < 8; j++) {
            int c = bn + warpN + j * 8 + tig * 2;
            if (c < N) {
                float2 v0 = make_float2(acc[i][j][0] + bias[c], acc[i][j][1] + bias[c + 1]);
                float2 v1 = make_float2(acc[i][j][2] + bias[c], acc[i][j][3] + bias[c + 1]);
                *(float2*)(C + (size_t)r * N + c) = v0;
                *(float2*)(C + (size_t)(r + 8) * N + c) = v1;
            }
        }
    }
}

// ---------------- row L2-normalize H (16384 x 256), one warp per row ----------------
__global__ void norm_rows_kernel(float* __restrict__ H)
{
    int warp = (blockIdx.x * blockDim.x + threadIdx.x) >> 5;
    int lane = threadIdx.x & 31;
    if (warp >= 16384) return;
    float* rowp = H + (size_t)warp * 256;
    float4 a = *(const float4*)(rowp + lane * 4);
    float4 b = *(const float4*)(rowp + 128 + lane * 4);
    float s = a.x * a.x + a.y * a.y + a.z * a.z + a.w * a.w
            + b.x * b.x + b.y * b.y + b.z * b.z + b.w * b.w;
#pragma unroll
    for (int o = 16; o; o >>= 1) s += __shfl_xor_sync(0xffffffffu, s, o);
    float inv = 1.0f / sqrtf(s);
    a.x *= inv; a.y *= inv; a.z *= inv; a.w *= inv;
    b.x *= inv; b.y *= inv; b.z *= inv; b.w *= inv;
    *(float4*)(rowp + lane * 4) = a;
    *(float4*)(rowp + 128 + lane * 4) = b;
}

// ---------------- scan phase 1: per-class ordered occurrence lists ----------------
__global__ void rank_kernel(const int* __restrict__ llabel,
                            int* __restrict__ occ, int* __restrict__ cnt)
{
    int c = blockIdx.x;
    int lane = threadIdx.x;
    int base = 0;
    for (int i0 = 0; i0 < 8192; i0 += 32) {
        int lab = llabel[i0 + lane];
        unsigned m = __ballot_sync(0xffffffffu, lab == c);
        if (lab == c) {
            int r = base + __popc(m & ((1u << lane) - 1u));
            occ[c * 8192 + r] = i0 + lane;
        }
        base += __popc(m);
    }
    if (lane == 0) cnt[c] = base;
}

// ---------------- scan phase 2: EMA over each class's occurrences ----------------
__global__ void ema_kernel(const float* __restrict__ H,
                           const int* __restrict__ occ, const int* __restrict__ cnt,
                           const float* __restrict__ mbank0, const float* __restrict__ start0,
                           float* __restrict__ MB, float* __restrict__ out_mbank)
{
    int c = blockIdx.x;
    int d = threadIdx.x;
    __shared__ int idxs[256];
    int n = cnt[c];
    float row = mbank0[c * 256 + d];
    bool started = (start0[c] != 0.0f);
    for (int r0 = 0; r0 < n; r0 += 256) {
        __syncthreads();
        if (r0 + d < n) idxs[d] = occ[c * 8192 + r0 + d];
        __syncthreads();
        int lim = min(256, n - r0);
#pragma unroll 4
        for (int j = 0; j < lim; j++) {
            float f = H[(size_t)idxs[j] * 256 + d];
            row = started ? fmaf(0.9f, row, 0.1f * f) : f;
            started = true;
        }
    }
    MB[c * 256 + d] = row;
    out_mbank[c * 256 + d] = row;
}

// ---------------- distances: lscores for labeled, UF = [ufeat | um | 0pad] ----------------
__global__ void dist_kernel(const float* __restrict__ H, const float* __restrict__ MB,
                            float* __restrict__ lscores, float* __restrict__ UF)
{
    __shared__ float mb[40 * 256];
    for (int i = threadIdx.x; i < 40 * 256; i += blockDim.x) mb[i] = MB[i];
    __syncthreads();

    int nwarp = (gridDim.x * blockDim.x) >> 5;
    int warp = (blockIdx.x * blockDim.x + threadIdx.x) >> 5;
    int lane = threadIdx.x & 31;

    for (int row = warp; row < 16384; row += nwarp) {
        float h[8];
#pragma unroll
        for (int k = 0; k < 8; k++) h[k] = H[(size_t)row * 256 + lane + 32 * k];
        if (row < 8192) {
            float best = 3.4e38f;
            for (int c = 0; c < 40; c++) {
                float s = 0.f;
#pragma unroll
                for (int k = 0; k < 8; k++) {
                    float dl = h[k] - mb[c * 256 + lane + 32 * k];
                    s = fmaf(dl, dl, s);
                }
#pragma unroll
                for (int o = 16; o; o >>= 1) s += __shfl_xor_sync(0xffffffffu, s, o);
                best = fminf(best, s);
            }
            if (lane == 0) lscores[row] = sqrtf(best);
        } else {
            int r = row - 8192;
#pragma unroll
            for (int k = 0; k < 8; k++)
                UF[(size_t)r * 320 + lane + 32 * k] = h[k];
            for (int c = 0; c < 40; c++) {
                float s = 0.f;
#pragma unroll
                for (int k = 0; k < 8; k++) {
                    float dl = h[k] - mb[c * 256 + lane + 32 * k];
                    s = fmaf(dl, dl, s);
                }
#pragma unroll
                for (int o = 16; o; o >>= 1) s += __shfl_xor_sync(0xffffffffu, s, o);
                if (lane == 0) UF[(size_t)r * 320 + 256 + c] = sqrtf(s);
            }
            if (lane < 24) UF[(size_t)r * 320 + 296 + lane] = 0.f;  // zero pad 296..319
        }
    }
}

// ---------------- BN stage 1: per-block partial column sums (deterministic) ----------------
__global__ void bn_part_kernel(const float* __restrict__ X, int cols,
                               float* __restrict__ ps, float* __restrict__ pq)
{
    int col = threadIdx.x;
    int r0 = blockIdx.x * 128;
    float s = 0.f, q = 0.f;
    for (int r = r0; r < r0 + 128; r++) {
        float v = X[(size_t)r * cols + col];
        s += v;
        q = fmaf(v, v, q);
    }
    ps[blockIdx.x * cols + col] = s;
    pq[blockIdx.x * cols + col] = q;
}

// ---------------- BN stage 2: fold 64 partials ----------------
__global__ void bn_stats_kernel(const float* __restrict__ ps, const float* __restrict__ pq,
                                int cols, float* __restrict__ mean, float* __restrict__ inv)
{
    int col = threadIdx.x;
    float s = 0.f, q = 0.f;
    for (int b = 0; b < 64; b++) { s += ps[b * cols + col]; q += pq[b * cols + col]; }
    float mu = s * (1.0f / 8192.0f);
    float var = q * (1.0f / 8192.0f) - mu * mu;
    mean[col] = mu;
    inv[col] = 1.0f / sqrtf(var + 1e-5f);
}

// ---------------- BN apply + ReLU (in place) ----------------
__global__ void bn_apply_kernel(float* __restrict__ X, int n, int cols,
                                const float* __restrict__ mean, const float* __restrict__ inv,
                                const float* __restrict__ g, const float* __restrict__ be)
{
    int idx = blockIdx.x * blockDim.x + threadIdx.x;
    if (idx < n) {
        int col = idx & (cols - 1);
        float v = (X[idx] - mean[col]) * inv[col] * g[col] + be[col];
        X[idx] = fmaxf(v, 0.f);
    }
}

// ---------------- final matvec ----------------
__global__ void gemm5_kernel(const float* __restrict__ U4, const float* __restrict__ W5,
                             const float* __restrict__ b5, float* __restrict__ out)
{
    int warp = (blockIdx.x * blockDim.x + threadIdx.x) >> 5;
    int lane = threadIdx.x & 31;
    if (warp >= 8192) return;
    float s = U4[(size_t)warp * 64 + lane] * W5[lane]
            + U4[(size_t)warp * 64 + 32 + lane] * W5[32 + lane];
#pragma unroll
    for (int o = 16; o; o >>= 1) s += __shfl_xor_sync(0xffffffffu, s, o);
    if (lane == 0) out[warp] = s + b5[0];
}

// ---------------- launcher ----------------
extern "C" void kernel_launch(void* const* d_in, const int* in_sizes, int n_in,
                              void* d_out, int out_size)
{
    const float* lufeat = (const float*)d_in[0];
    const int*   llabel = (const int*)  d_in[1];
    const float* W1 = (const float*)d_in[2];
    const float* b1 = (const float*)d_in[3];
    const float* W2 = (const float*)d_in[4];
    const float* b2 = (const float*)d_in[5];
    const float* W3 = (const float*)d_in[6];
    const float* b3 = (const float*)d_in[7];
    const float* W4 = (const float*)d_in[8];
    const float* b4 = (const float*)d_in[9];
    const float* W5 = (const float*)d_in[10];
    const float* b5 = (const float*)d_in[11];
    const float* g1 = (const float*)d_in[12];
    const float* be1 = (const float*)d_in[13];
    const float* g2 = (const float*)d_in[14];
    const float* be2 = (const float*)d_in[15];
    const float* mbank0 = (const float*)d_in[16];
    const float* start0 = (const float*)d_in[17];
    float* out = (float*)d_out;

    float *H, *MB, *UF, *Y3, *Y4, *PS, *PQ, *MEAN, *INV, *W12, *B12, *ZERO;
    int *OCC, *CNT;
    __nv_bfloat16 *W2h, *W2l, *W3h, *W3l, *W4h, *W4l, *W12h, *W12l;
    cudaGetSymbolAddress((void**)&H,  g_H);
    cudaGetSymbolAddress((void**)&MB, g_MB);
    cudaGetSymbolAddress((void**)&UF, g_UF);
    cudaGetSymbolAddress((void**)&Y3, g_Y3);
    cudaGetSymbolAddress((void**)&Y4, g_Y4);
    cudaGetSymbolAddress((void**)&PS, g_PS);
    cudaGetSymbolAddress((void**)&PQ, g_PQ);
    cudaGetSymbolAddress((void**)&MEAN, g_MEAN);
    cudaGetSymbolAddress((void**)&INV,  g_INV);
    cudaGetSymbolAddress((void**)&OCC, g_OCC);
    cudaGetSymbolAddress((void**)&CNT, g_CNT);
    cudaGetSymbolAddress((void**)&W12, g_W12);
    cudaGetSymbolAddress((void**)&B12, g_B12);
    cudaGetSymbolAddress((void**)&ZERO, g_ZERO);
    cudaGetSymbolAddress((void**)&W2h, g_W2h); cudaGetSymbolAddress((void**)&W2l, g_W2l);
    cudaGetSymbolAddress((void**)&W3h, g_W3h); cudaGetSymbolAddress((void**)&W3l, g_W3l);
    cudaGetSymbolAddress((void**)&W4h, g_W4h); cudaGetSymbolAddress((void**)&W4l, g_W4l);
    cudaGetSymbolAddress((void**)&W12h, g_W12h); cudaGetSymbolAddress((void**)&W12l, g_W12l);

    const int SMEM_BYTES = 81920;
    cudaFuncSetAttribute(mma_gemm, cudaFuncAttributeMaxDynamicSharedMemorySize, SMEM_BYTES);

    // weight splits (transposed) for W2/W3/W4
    split_all_kernel<<<960, 256>>>(W2, W3, W4, W2h, W2l, W3h, W3l, W4h, W4l);
    rank_kernel<<<40, 32>>>(llabel, OCC, CNT);

    // W12 = W1 @ W2 (f32 out, zero bias), b12 = b1@W2 + b2, split W12 transposed
    bias12_kernel<<<1, 256>>>(b1, W2, b2, B12);
    mma_gemm<<<dim3(2, 8), 256, SMEM_BYTES>>>(W1, 512, W2h, W2l, ZERO, W12, 256, 512);
    split_w12_kernel<<<1024, 256>>>(W12, W12h, W12l);

    // h = lufeat @ W12 + b12 ; normalize rows
    mma_gemm<<<dim3(2, 128), 256, SMEM_BYTES>>>(lufeat, 1024, W12h, W12l, B12, H, 256, 1024);
    norm_rows_kernel<<<2048, 256>>>(H);

    // memory bank EMA
    ema_kernel<<<40, 256>>>(H, OCC, CNT, mbank0, start0, MB, out + 16384);

    // distances
    dist_kernel<<<128, 256>>>(H, MB, out, UF);

    // layer 3: UF(8192x296, stride 320, zero-padded) @ W3 (Kp=320)
    mma_gemm<<<dim3(2, 64), 256, SMEM_BYTES>>>(UF, 320, W3h, W3l, b3, Y3, 256, 320);
    bn_part_kernel<<<64, 256>>>(Y3, 256, PS, PQ);
    bn_stats_kernel<<<1, 256>>>(PS, PQ, 256, MEAN, INV);
    bn_apply_kernel<<<(8192 * 256 + 255) / 256, 256>>>(Y3, 8192 * 256, 256, MEAN, INV, g1, be1);

    // layer 4: Y3(8192x256) @ W4 (N pad 128, Kp=256)
    mma_gemm<<<dim3(1, 64), 256, SMEM_BYTES>>>(Y3, 256, W4h, W4l, b4, Y4, 64, 256);
    bn_part_kernel<<<64, 64>>>(Y4, 64, PS, PQ);
    bn_stats_kernel<<<1, 64>>>(PS, PQ, 64, MEAN, INV);
    bn_apply_kernel<<<(8192 * 64 + 255) / 256, 256>>>(Y4, 8192 * 64, 64, MEAN, INV, g2, be2);

    // uscores
    gemm5_kernel<<<1024, 256>>>(Y4, W5, b5, out + 8192);
}

// round 17
// speedup vs baseline: 5.0153x; 1.1262x over previous
#include <cuda_runtime.h>
#include <cuda_bf16.h>
#include <cstdint>
#include <math.h>

// ---------------- scratch (device globals; no allocation allowed) ----------------
__device__ float g_H [16384 * 256];   // X@W12+b12, then normalized in place
__device__ float g_MB[40 * 256];      // memory bank after scan
__device__ float g_UF[8192 * 320];    // concat(ufeat, um), padded 296->320
__device__ float g_Y3[8192 * 256];
__device__ float g_Y4[8192 * 64];
__device__ float g_PS[64 * 256];
__device__ float g_PQ[64 * 256];
__device__ float g_MEAN[256];
__device__ float g_INV[256];
__device__ int   g_OCC[40 * 8192];
__device__ int   g_CNT[40];
__device__ float g_W12P[4 * 1024 * 256]; // split-K partials of W1@W2
__device__ float g_B12[256];             // b1@W2 + b2
// bf16 hi/lo split weights, TRANSPOSED layout: W^T[n][k], row stride = Kp
__device__ __align__(16) __nv_bfloat16 g_W2h[256 * 512],   g_W2l[256 * 512];
__device__ __align__(16) __nv_bfloat16 g_W3h[256 * 320],   g_W3l[256 * 320];   // K pad 296->320
__device__ __align__(16) __nv_bfloat16 g_W4h[128 * 256],   g_W4l[128 * 256];   // N pad 64->128
__device__ __align__(16) __nv_bfloat16 g_W12h[256 * 1024], g_W12l[256 * 1024]; // [256 n][1024 k]

// ---------------- fused: split W2/W3/W4 into transposed bf16 hi/lo ----------------
__global__ void split_all_kernel(
    const float* __restrict__ W2, const float* __restrict__ W3, const float* __restrict__ W4,
    __nv_bfloat16* __restrict__ W2h, __nv_bfloat16* __restrict__ W2l,
    __nv_bfloat16* __restrict__ W3h, __nv_bfloat16* __restrict__ W3l,
    __nv_bfloat16* __restrict__ W4h, __nv_bfloat16* __restrict__ W4l)
{
    int b = blockIdx.x;
    const float* W; __nv_bfloat16 *Wh, *Wl; int K, N, Kp, idx0;
    if (b < 512)      { W = W2; Wh = W2h; Wl = W2l; K = 512; N = 256; Kp = 512; idx0 = b * 256; }
    else if (b < 832) { W = W3; Wh = W3h; Wl = W3l; K = 296; N = 256; Kp = 320; idx0 = (b - 512) * 256; }
    else              { W = W4; Wh = W4h; Wl = W4l; K = 256; N = 64;  Kp = 256; idx0 = (b - 832) * 256; }
    int idx = idx0 + threadIdx.x;
    int n = idx / Kp, k = idx - n * Kp;
    float v = (k < K && n < N) ? W[k * N + n] : 0.f;
    __nv_bfloat16 h = __float2bfloat16(v);
    float r = v - __bfloat162float(h);
    Wh[idx] = h;
    Wl[idx] = __float2bfloat16(r);
}

// ---------------- reduce 4 split-K partials of W12, split+transpose to bf16 hi/lo ----
__global__ void w12_reduce_split(const float* __restrict__ P,
                                 __nv_bfloat16* __restrict__ Wh, __nv_bfloat16* __restrict__ Wl)
{
    int idx = blockIdx.x * 256 + threadIdx.x;    // over 1024*256
    int k = idx >> 8, n = idx & 255;
    float v = P[idx] + P[262144 + idx] + P[524288 + idx] + P[786432 + idx];
    __nv_bfloat16 h = __float2bfloat16(v);
    float r = v - __bfloat162float(h);
    Wh[n * 1024 + k] = h;
    Wl[n * 1024 + k] = __float2bfloat16(r);
}

// ---------------- b12 = b1 @ W2 + b2 ----------------
__global__ void bias12_kernel(const float* __restrict__ b1, const float* __restrict__ W2,
                              const float* __restrict__ b2, float* __restrict__ B12)
{
    int n = threadIdx.x;   // 256
    float s = b2[n];
    for (int k = 0; k < 512; k++) s = fmaf(b1[k], W2[k * 256 + n], s);
    B12[n] = s;
}

// ---------------- ldmatrix helpers ----------------
__device__ __forceinline__ void ldsm_x4(unsigned int* r, const void* p) {
    unsigned int addr = (unsigned int)__cvta_generic_to_shared(p);
    asm volatile("ldmatrix.sync.aligned.m8n8.x4.shared.b16 {%0,%1,%2,%3}, [%4];"
        : "=r"(r[0]), "=r"(r[1]), "=r"(r[2]), "=r"(r[3]) : "r"(addr));
}

#define MMA3(d, ahv, bh0, bh1, bl0, bl1, alv)                                        \
    asm volatile("mma.sync.aligned.m16n8k16.row.col.f32.bf16.bf16.f32 "              \
        "{%0,%1,%2,%3}, {%4,%5,%6,%7}, {%8,%9}, {%0,%1,%2,%3};"                      \
        : "+f"(d[0]), "+f"(d[1]), "+f"(d[2]), "+f"(d[3])                             \
        : "r"(ahv[0]), "r"(ahv[1]), "r"(ahv[2]), "r"(ahv[3]), "r"(bh0), "r"(bh1));   \
    asm volatile("mma.sync.aligned.m16n8k16.row.col.f32.bf16.bf16.f32 "              \
        "{%0,%1,%2,%3}, {%4,%5,%6,%7}, {%8,%9}, {%0,%1,%2,%3};"                      \
        : "+f"(d[0]), "+f"(d[1]), "+f"(d[2]), "+f"(d[3])                             \
        : "r"(ahv[0]), "r"(ahv[1]), "r"(ahv[2]), "r"(ahv[3]), "r"(bl0), "r"(bl1));   \
    asm volatile("mma.sync.aligned.m16n8k16.row.col.f32.bf16.bf16.f32 "              \
        "{%0,%1,%2,%3}, {%4,%5,%6,%7}, {%8,%9}, {%0,%1,%2,%3};"                      \
        : "+f"(d[0]), "+f"(d[1]), "+f"(d[2]), "+f"(d[3])                             \
        : "r"(alv[0]), "r"(alv[1]), "r"(alv[2]), "r"(alv[3]), "r"(bh0), "r"(bh1));

// ---------------- bf16-split tensor-core GEMM: C = A(f32) @ B + bias ------------------
// B given TRANSPOSED (B^T[n][k], row stride Kp). BM=128, BN=128, BK=32.
__global__ __launch_bounds__(256, 2) void mma_gemm(
    const float* __restrict__ A, int lda,
    const __nv_bfloat16* __restrict__ BhT, const __nv_bfloat16* __restrict__ BlT,
    const float* __restrict__ bias, float* __restrict__ C,
    int N, int Kp)
{
    extern __shared__ __nv_bfloat16 sm[];
    __nv_bfloat16* sAh = sm;
    __nv_bfloat16* sAl = sm + 10240;
    __nv_bfloat16* sBh = sm + 20480;
    __nv_bfloat16* sBl = sm + 30720;

    const int tid = threadIdx.x;
    const int lane = tid & 31, warp = tid >> 5;
    const int g = lane >> 2, tig = lane & 3;
    const int warpM = (warp >> 1) * 32;
    const int warpN = (warp & 1) * 64;
    const int bm = blockIdx.y * 128;
    const int bn = blockIdx.x * 128;
    const int lm_row = lane & 15;
    const int lm_koff = (lane >> 4) * 8;

    float acc[2][8][4];
#pragma unroll
    for (int i = 0; i < 2; i++)
#pragma unroll
        for (int j = 0; j < 8; j++)
#pragma unroll
            for (int q = 0; q < 4; q++) acc[i][j][q] = 0.f;

    const int nk = Kp / 32;
    float4 ra[4];

    auto loadA = [&](int k0) {
#pragma unroll
        for (int i = 0; i < 4; i++) {
            int v = tid + 256 * i;
            int r = v >> 3, c = (v & 7) * 4;
            ra[i] = *(const float4*)(A + (size_t)(bm + r) * lda + k0 + c);
        }
    };
    auto storeA = [&](int buf) {
        __nv_bfloat16* dh = sAh + buf * 5120;
        __nv_bfloat16* dl = sAl + buf * 5120;
#pragma unroll
        for (int i = 0; i < 4; i++) {
            int v = tid + 256 * i;
            int r = v >> 3, c = (v & 7) * 4;
            float f[4] = { ra[i].x, ra[i].y, ra[i].z, ra[i].w };
            __nv_bfloat16 h[4], l[4];
#pragma unroll
            for (int q = 0; q < 4; q++) {
                h[q] = __float2bfloat16(f[q]);
                l[q] = __float2bfloat16(f[q] - __bfloat162float(h[q]));
            }
            __nv_bfloat162 hh0; hh0.x = h[0]; hh0.y = h[1];
            __nv_bfloat162 hh1; hh1.x = h[2]; hh1.y = h[3];
            __nv_bfloat162 ll0; ll0.x = l[0]; ll0.y = l[1];
            __nv_bfloat162 ll1; ll1.x = l[2]; ll1.y = l[3];
            *(__nv_bfloat162*)&dh[r * 40 + c]     = hh0;
            *(__nv_bfloat162*)&dh[r * 40 + c + 2] = hh1;
            *(__nv_bfloat162*)&dl[r * 40 + c]     = ll0;
            *(__nv_bfloat162*)&dl[r * 40 + c + 2] = ll1;
        }
    };
    auto cpB = [&](int k0, int buf) {
#pragma unroll
        for (int i = 0; i < 2; i++) {
            int v = tid + 256 * i;
            int n = v >> 2, kc = (v & 3) * 8;
            const __nv_bfloat16* gh = BhT + (size_t)(bn + n) * Kp + k0 + kc;
            const __nv_bfloat16* gl = BlT + (size_t)(bn + n) * Kp + k0 + kc;
            unsigned dsth = (unsigned)__cvta_generic_to_shared(&sBh[buf * 5120 + n * 40 + kc]);
            unsigned dstl = (unsigned)__cvta_generic_to_shared(&sBl[buf * 5120 + n * 40 + kc]);
            asm volatile("cp.async.ca.shared.global [%0], [%1], 16;" :: "r"(dsth), "l"(gh));
            asm volatile("cp.async.ca.shared.global [%0], [%1], 16;" :: "r"(dstl), "l"(gl));
        }
        asm volatile("cp.async.commit_group;");
    };

    loadA(0); cpB(0, 0); storeA(0);
    asm volatile("cp.async.wait_group 0;");
    __syncthreads();

    for (int t = 0; t < nk; t++) {
        int cur = t & 1, nxt = cur ^ 1;
        bool more = (t + 1 < nk);
        if (more) { loadA((t + 1) * 32); cpB((t + 1) * 32, nxt); }

        const __nv_bfloat16* pAh = sAh + cur * 5120;
        const __nv_bfloat16* pAl = sAl + cur * 5120;
        const __nv_bfloat16* pBh = sBh + cur * 5120;
        const __nv_bfloat16* pBl = sBl + cur * 5120;

#pragma unroll
        for (int kk = 0; kk < 32; kk += 16) {
            unsigned int ah[2][4], al[2][4];
#pragma unroll
            for (int i = 0; i < 2; i++) {
                ldsm_x4(ah[i], pAh + (warpM + i * 16 + lm_row) * 40 + kk + lm_koff);
                ldsm_x4(al[i], pAl + (warpM + i * 16 + lm_row) * 40 + kk + lm_koff);
            }
#pragma unroll
            for (int jj = 0; jj < 4; jj++) {
                unsigned int bh[4], bl[4];
                ldsm_x4(bh, pBh + (warpN + jj * 16 + lm_row) * 40 + kk + lm_koff);
                ldsm_x4(bl, pBl + (warpN + jj * 16 + lm_row) * 40 + kk + lm_koff);
#pragma unroll
                for (int odd = 0; odd < 2; odd++) {
                    int j = jj * 2 + odd;
#pragma unroll
                    for (int i = 0; i < 2; i++) {
                        float* d = acc[i][j];
                        MMA3(d, ah[i], bh[odd], bh[odd + 2], bl[odd], bl[odd + 2], al[i]);
                    }
                }
            }
        }
        if (more) { storeA(nxt); asm volatile("cp.async.wait_group 0;"); }
        __syncthreads();
    }

#pragma unroll
    for (int i = 0; i < 2; i++) {
        int r = bm + warpM + i * 16 + g;
#pragma unroll
        for (int j = 0; j < 8; j++) {
            int c = bn + warpN + j * 8 + tig * 2;
            if (c < N) {
                float2 v0 = make_float2(acc[i][j][0] + bias[c], acc[i][j][1] + bias[c + 1]);
                float2 v1 = make_float2(acc[i][j][2] + bias[c], acc[i][j][3] + bias[c + 1]);
                *(float2*)(C + (size_t)r * N + c) = v0;
                *(float2*)(C + (size_t)(r + 8) * N + c) = v1;
            }
        }
    }
}

// ---------------- split-K variant: z-dim slices K; writes raw partials (no bias) ----
// Used for W12 = W1 @ W2: M=1024, N=256, Kslice per z. Partial z at P + z*M*N.
__global__ __launch_bounds__(256, 2) void mma_gemm_sk(
    const float* __restrict__ A, int lda,
    const __nv_bfloat16* __restrict__ BhT, const __nv_bfloat16* __restrict__ BlT,
    float* __restrict__ P, int M, int N, int ldb, int Kslice)
{
    extern __shared__ __nv_bfloat16 sm[];
    __nv_bfloat16* sAh = sm;
    __nv_bfloat16* sAl = sm + 10240;
    __nv_bfloat16* sBh = sm + 20480;
    __nv_bfloat16* sBl = sm + 30720;

    const int tid = threadIdx.x;
    const int lane = tid & 31, warp = tid >> 5;
    const int g = lane >> 2, tig = lane & 3;
    const int warpM = (warp >> 1) * 32;
    const int warpN = (warp & 1) * 64;
    const int bm = blockIdx.y * 128;
    const int bn = blockIdx.x * 128;
    const int koff = blockIdx.z * Kslice;
    float* C = P + (size_t)blockIdx.z * M * N;
    const int lm_row = lane & 15;
    const int lm_koff = (lane >> 4) * 8;

    float acc[2][8][4];
#pragma unroll
    for (int i = 0; i < 2; i++)
#pragma unroll
        for (int j = 0; j < 8; j++)
#pragma unroll
            for (int q = 0; q < 4; q++) acc[i][j][q] = 0.f;

    const int nk = Kslice / 32;
    float4 ra[4];

    auto loadA = [&](int k0) {
#pragma unroll
        for (int i = 0; i < 4; i++) {
            int v = tid + 256 * i;
            int r = v >> 3, c = (v & 7) * 4;
            ra[i] = *(const float4*)(A + (size_t)(bm + r) * lda + koff + k0 + c);
        }
    };
    auto storeA = [&](int buf) {
        __nv_bfloat16* dh = sAh + buf * 5120;
        __nv_bfloat16* dl = sAl + buf * 5120;
#pragma unroll
        for (int i = 0; i < 4; i++) {
            int v = tid + 256 * i;
            int r = v >> 3, c = (v & 7) * 4;
            float f[4] = { ra[i].x, ra[i].y, ra[i].z, ra[i].w };
            __nv_bfloat16 h[4], l[4];
#pragma unroll
            for (int q = 0; q < 4; q++) {
                h[q] = __float2bfloat16(f[q]);
                l[q] = __float2bfloat16(f[q] - __bfloat162float(h[q]));
            }
            __nv_bfloat162 hh0; hh0.x = h[0]; hh0.y = h[1];
            __nv_bfloat162 hh1; hh1.x = h[2]; hh1.y = h[3];
            __nv_bfloat162 ll0; ll0.x = l[0]; ll0.y = l[1];
            __nv_bfloat162 ll1; ll1.x = l[2]; ll1.y = l[3];
            *(__nv_bfloat162*)&dh[r * 40 + c]     = hh0;
            *(__nv_bfloat162*)&dh[r * 40 + c + 2] = hh1;
            *(__nv_bfloat162*)&dl[r * 40 + c]     = ll0;
            *(__nv_bfloat162*)&dl[r * 40 + c + 2] = ll1;
        }
    };
    auto cpB = [&](int k0, int buf) {
#pragma unroll
        for (int i = 0; i < 2; i++) {
            int v = tid + 256 * i;
            int n = v >> 2, kc = (v & 3) * 8;
            const __nv_bfloat16* gh = BhT + (size_t)(bn + n) * ldb + koff + k0 + kc;
            const __nv_bfloat16* gl = BlT + (size_t)(bn + n) * ldb + koff + k0 + kc;
            unsigned dsth = (unsigned)__cvta_generic_to_shared(&sBh[buf * 5120 + n * 40 + kc]);
            unsigned dstl = (unsigned)__cvta_generic_to_shared(&sBl[buf * 5120 + n * 40 + kc]);
            asm volatile("cp.async.ca.shared.global [%0], [%1], 16;" :: "r"(dsth), "l"(gh));
            asm volatile("cp.async.ca.shared.global [%0], [%1], 16;" :: "r"(dstl), "l"(gl));
        }
        asm volatile("cp.async.commit_group;");
    };

    loadA(0); cpB(0, 0); storeA(0);
    asm volatile("cp.async.wait_group 0;");
    __syncthreads();

    for (int t = 0; t < nk; t++) {
        int cur = t & 1, nxt = cur ^ 1;
        bool more = (t + 1 < nk);
        if (more) { loadA((t + 1) * 32); cpB((t + 1) * 32, nxt); }

        const __nv_bfloat16* pAh = sAh + cur * 5120;
        const __nv_bfloat16* pAl = sAl + cur * 5120;
        const __nv_bfloat16* pBh = sBh + cur * 5120;
        const __nv_bfloat16* pBl = sBl + cur * 5120;

#pragma unroll
        for (int kk = 0; kk < 32; kk += 16) {
            unsigned int ah[2][4], al[2][4];
#pragma unroll
            for (int i = 0; i < 2; i++) {
                ldsm_x4(ah[i], pAh + (warpM + i * 16 + lm_row) * 40 + kk + lm_koff);
                ldsm_x4(al[i], pAl + (warpM + i * 16 + lm_row) * 40 + kk + lm_koff);
            }
#pragma unroll
            for (int jj = 0; jj < 4; jj++) {
                unsigned int bh[4], bl[4];
                ldsm_x4(bh, pBh + (warpN + jj * 16 + lm_row) * 40 + kk + lm_koff);
                ldsm_x4(bl, pBl + (warpN + jj * 16 + lm_row) * 40 + kk + lm_koff);
#pragma unroll
                for (int odd = 0; odd < 2; odd++) {
                    int j = jj * 2 + odd;
#pragma unroll
                    for (int i = 0; i < 2; i++) {
                        float* d = acc[i][j];
                        MMA3(d, ah[i], bh[odd], bh[odd + 2], bl[odd], bl[odd + 2], al[i]);
                    }
                }
            }
        }
        if (more) { storeA(nxt); asm volatile("cp.async.wait_group 0;"); }
        __syncthreads();
    }

#pragma unroll
    for (int i = 0; i < 2; i++) {
        int r = bm + warpM + i * 16 + g;
#pragma unroll
        for (int j = 0; j < 8; j++) {
            int c = bn + warpN + j * 8 + tig * 2;
            *(float2*)(C + (size_t)r * N + c) = make_float2(acc[i][j][0], acc[i][j][1]);
            *(float2*)(C + (size_t)(r + 8) * N + c) = make_float2(acc[i][j][2], acc[i][j][3]);
        }
    }
}

// ---------------- BN=64 variant (layer 4): BM=128, BN=64, BK=32 ----------------------
__global__ __launch_bounds__(256, 2) void mma_gemm_n64(
    const float* __restrict__ A, int lda,
    const __nv_bfloat16* __restrict__ BhT, const __nv_bfloat16* __restrict__ BlT,
    const float* __restrict__ bias, float* __restrict__ C,
    int N, int Kp)
{
    extern __shared__ __nv_bfloat16 sm[];
    __nv_bfloat16* sAh = sm;            // [2][128][40]
    __nv_bfloat16* sAl = sm + 10240;
    __nv_bfloat16* sBh = sm + 20480;    // [2][64][40]
    __nv_bfloat16* sBl = sm + 25600;

    const int tid = threadIdx.x;
    const int lane = tid & 31, warp = tid >> 5;
    const int g = lane >> 2, tig = lane & 3;
    const int warpM = (warp >> 1) * 32;
    const int warpN = (warp & 1) * 32;
    const int bm = blockIdx.y * 128;
    const int lm_row = lane & 15;
    const int lm_koff = (lane >> 4) * 8;

    float acc[2][4][4];
#pragma unroll
    for (int i = 0; i < 2; i++)
#pragma unroll
        for (int j = 0; j < 4; j++)
#pragma unroll
            for (int q = 0; q < 4; q++) acc[i][j][q] = 0.f;

    const int nk = Kp / 32;
    float4 ra[4];

    auto loadA = [&](int k0) {
#pragma unroll
        for (int i = 0; i < 4; i++) {
            int v = tid + 256 * i;
            int r = v >> 3, c = (v & 7) * 4;
            ra[i] = *(const float4*)(A + (size_t)(bm + r) * lda + k0 + c);
        }
    };
    auto storeA = [&](int buf) {
        __nv_bfloat16* dh = sAh + buf * 5120;
        __nv_bfloat16* dl = sAl + buf * 5120;
#pragma unroll
        for (int i = 0; i < 4; i++) {
            int v = tid + 256 * i;
            int r = v >> 3, c = (v & 7) * 4;
            float f[4] = { ra[i].x, ra[i].y, ra[i].z, ra[i].w };
            __nv_bfloat16 h[4], l[4];
#pragma unroll
            for (int q = 0; q < 4; q++) {
                h[q] = __float2bfloat16(f[q]);
                l[q] = __float2bfloat16(f[q] - __bfloat162float(h[q]));
            }
            __nv_bfloat162 hh0; hh0.x = h[0]; hh0.y = h[1];
            __nv_bfloat162 hh1; hh1.x = h[2]; hh1.y = h[3];
            __nv_bfloat162 ll0; ll0.x = l[0]; ll0.y = l[1];
            __nv_bfloat162 ll1; ll1.x = l[2]; ll1.y = l[3];
            *(__nv_bfloat162*)&dh[r * 40 + c]     = hh0;
            *(__nv_bfloat162*)&dh[r * 40 + c + 2] = hh1;
            *(__nv_bfloat162*)&dl[r * 40 + c]     = ll0;
            *(__nv_bfloat162*)&dl[r * 40 + c + 2] = ll1;
        }
    };
    auto cpB = [&](int k0, int buf) {
        int n = tid >> 2, kc = (tid & 3) * 8;   // 64 rows x 32 bf16
        const __nv_bfloat16* gh = BhT + (size_t)n * Kp + k0 + kc;
        const __nv_bfloat16* gl = BlT + (size_t)n * Kp + k0 + kc;
        unsigned dsth = (unsigned)__cvta_generic_to_shared(&sBh[buf * 2560 + n * 40 + kc]);
        unsigned dstl = (unsigned)__cvta_generic_to_shared(&sBl[buf * 2560 + n * 40 + kc]);
        asm volatile("cp.async.ca.shared.global [%0], [%1], 16;" :: "r"(dsth), "l"(gh));
        asm volatile("cp.async.ca.shared.global [%0], [%1], 16;" :: "r"(dstl), "l"(gl));
        asm volatile("cp.async.commit_group;");
    };

    loadA(0); cpB(0, 0); storeA(0);
    asm volatile("cp.async.wait_group 0;");
    __syncthreads();

    for (int t = 0; t < nk; t++) {
        int cur = t & 1, nxt = cur ^ 1;
        bool more = (t + 1 < nk);
        if (more) { loadA((t + 1) * 32); cpB((t + 1) * 32, nxt); }

        const __nv_bfloat16* pAh = sAh + cur * 5120;
        const __nv_bfloat16* pAl = sAl + cur * 5120;
        const __nv_bfloat16* pBh = sBh + cur * 2560;
        const __nv_bfloat16* pBl = sBl + cur * 2560;

#pragma unroll
        for (int kk = 0; kk < 32; kk += 16) {
            unsigned int ah[2][4], al[2][4];
#pragma unroll
            for (int i = 0; i < 2; i++) {
                ldsm_x4(ah[i], pAh + (warpM + i * 16 + lm_row) * 40 + kk + lm_koff);
                ldsm_x4(al[i], pAl + (warpM + i * 16 + lm_row) * 40 + kk + lm_koff);
            }
#pragma unroll
            for (int jj = 0; jj < 2; jj++) {
                unsigned int bh[4], bl[4];
                ldsm_x4(bh, pBh + (warpN + jj * 16 + lm_row) * 40 + kk + lm_koff);
                ldsm_x4(bl, pBl + (warpN + jj * 16 + lm_row) * 40 + kk + lm_koff);
#pragma unroll
                for (int odd = 0; odd < 2; odd++) {
                    int j = jj * 2 + odd;
#pragma unroll
                    for (int i = 0; i < 2; i++) {
                        float* d = acc[i][j];
                        MMA3(d, ah[i], bh[odd], bh[odd + 2], bl[odd], bl[odd + 2], al[i]);
                    }
                }
            }
        }
        if (more) { storeA(nxt); asm volatile("cp.async.wait_group 0;"); }
        __syncthreads();
    }

#pragma unroll
    for (int i = 0; i < 2; i++) {
        int r = bm + warpM + i * 16 + g;
#pragma unroll
        for (int j = 0; j < 4; j++) {
            int c = warpN + j * 8 + tig * 2;
            if (c < N) {
                float2 v0 = make_float2(acc[i][j][0] + bias[c], acc[i][j][1] + bias[c + 1]);
                float2 v1 = make_float2(acc[i][j][2] + bias[c], acc[i][j][3] + bias[c + 1]);
                *(float2*)(C + (size_t)r * N + c) = v0;
                *(float2*)(C + (size_t)(r + 8) * N + c) = v1;
            }
        }
    }
}

// ---------------- row L2-normalize H (16384 x 256), one warp per row ----------------
__global__ void norm_rows_kernel(float* __restrict__ H)
{
    int warp = (blockIdx.x * blockDim.x + threadIdx.x) >> 5;
    int lane = threadIdx.x & 31;
    if (warp >= 16384) return;
    float* rowp = H + (size_t)warp * 256;
    float4 a = *(const float4*)(rowp + lane * 4);
    float4 b = *(const float4*)(rowp + 128 + lane * 4);
    float s = a.x * a.x + a.y * a.y + a.z * a.z + a.w * a.w
            + b.x * b.x + b.y * b.y + b.z * b.z + b.w * b.w;
#pragma unroll
    for (int o = 16; o; o >>= 1) s += __shfl_xor_sync(0xffffffffu, s, o);
    float inv = 1.0f / sqrtf(s);
    a.x *= inv; a.y *= inv; a.z *= inv; a.w *= inv;
    b.x *= inv; b.y *= inv; b.z *= inv; b.w *= inv;
    *(float4*)(rowp + lane * 4) = a;
    *(float4*)(rowp + 128 + lane * 4) = b;
}

// ---------------- scan phase 1: per-class ordered occurrence lists ----------------
__global__ void rank_kernel(const int* __restrict__ llabel,
                            int* __restrict__ occ, int* __restrict__ cnt)
{
    int c = blockIdx.x;
    int lane = threadIdx.x;
    int base = 0;
#pragma unroll 4
    for (int i0 = 0; i0 < 8192; i0 += 32) {
        int lab = llabel[i0 + lane];
        unsigned m = __ballot_sync(0xffffffffu, lab == c);
        if (lab == c) {
            int r = base + __popc(m & ((1u << lane) - 1u));
            occ[c * 8192 + r] = i0 + lane;
        }
        base += __popc(m);
    }
    if (lane == 0) cnt[c] = base;
}

// ---------------- scan phase 2: EMA over each class's occurrences ----------------
__global__ void ema_kernel(const float* __restrict__ H,
                           const int* __restrict__ occ, const int* __restrict__ cnt,
                           const float* __restrict__ mbank0, const float* __restrict__ start0,
                           float* __restrict__ MB, float* __restrict__ out_mbank)
{
    int c = blockIdx.x;
    int d = threadIdx.x;
    __shared__ int idxs[256];
    int n = cnt[c];
    float row = mbank0[c * 256 + d];
    bool started = (start0[c] != 0.0f);
    for (int r0 = 0; r0 < n; r0 += 256) {
        __syncthreads();
        if (r0 + d < n) idxs[d] = occ[c * 8192 + r0 + d];
        __syncthreads();
        int lim = min(256, n - r0);
#pragma unroll 4
        for (int j = 0; j < lim; j++) {
            float f = H[(size_t)idxs[j] * 256 + d];
            row = started ? fmaf(0.9f, row, 0.1f * f) : f;
            started = true;
        }
    }
    MB[c * 256 + d] = row;
    out_mbank[c * 256 + d] = row;
}

// ---------------- distances: lscores for labeled, UF = [ufeat | um | 0pad] ----------------
__global__ void dist_kernel(const float* __restrict__ H, const float* __restrict__ MB,
                            float* __restrict__ lscores, float* __restrict__ UF)
{
    __shared__ float mb[40 * 256];
    for (int i = threadIdx.x; i < 40 * 256; i += blockDim.x) mb[i] = MB[i];
    __syncthreads();

    int nwarp = (gridDim.x * blockDim.x) >> 5;
    int warp = (blockIdx.x * blockDim.x + threadIdx.x) >> 5;
    int lane = threadIdx.x & 31;

    for (int row = warp; row < 16384; row += nwarp) {
        float h[8];
#pragma unroll
        for (int k = 0; k < 8; k++) h[k] = H[(size_t)row * 256 + lane + 32 * k];
        if (row < 8192) {
            float best = 3.4e38f;
            for (int c = 0; c < 40; c++) {
                float s = 0.f;
#pragma unroll
                for (int k = 0; k < 8; k++) {
                    float dl = h[k] - mb[c * 256 + lane + 32 * k];
                    s = fmaf(dl, dl, s);
                }
#pragma unroll
                for (int o = 16; o; o >>= 1) s += __shfl_xor_sync(0xffffffffu, s, o);
                best = fminf(best, s);
            }
            if (lane == 0) lscores[row] = sqrtf(best);
        } else {
            int r = row - 8192;
#pragma unroll
            for (int k = 0; k < 8; k++)
                UF[(size_t)r * 320 + lane + 32 * k] = h[k];
            for (int c = 0; c < 40; c++) {
                float s = 0.f;
#pragma unroll
                for (int k = 0; k < 8; k++) {
                    float dl = h[k] - mb[c * 256 + lane + 32 * k];
                    s = fmaf(dl, dl, s);
                }
#pragma unroll
                for (int o = 16; o; o >>= 1) s += __shfl_xor_sync(0xffffffffu, s, o);
                if (lane == 0) UF[(size_t)r * 320 + 256 + c] = sqrtf(s);
            }
            if (lane < 24) UF[(size_t)r * 320 + 296 + lane] = 0.f;  // zero pad 296..319
        }
    }
}

// ---------------- BN stage 1: per-block partial column sums (deterministic) ----------------
__global__ void bn_part_kernel(const float* __restrict__ X, int cols,
                               float* __restrict__ ps, float* __restrict__ pq)
{
    int col = threadIdx.x;
    int r0 = blockIdx.x * 128;
    float s = 0.f, q = 0.f;
    for (int r = r0; r < r0 + 128; r++) {
        float v = X[(size_t)r * cols + col];
        s += v;
        q = fmaf(v, v, q);
    }
    ps[blockIdx.x * cols + col] = s;
    pq[blockIdx.x * cols + col] = q;
}

// ---------------- BN stage 2: fold 64 partials ----------------
__global__ void bn_stats_kernel(const float* __restrict__ ps, const float* __restrict__ pq,
                                int cols, float* __restrict__ mean, float* __restrict__ inv)
{
    int col = threadIdx.x;
    float s = 0.f, q = 0.f;
    for (int b = 0; b < 64; b++) { s += ps[b * cols + col]; q += pq[b * cols + col]; }
    float mu = s * (1.0f / 8192.0f);
    float var = q * (1.0f / 8192.0f) - mu * mu;
    mean[col] = mu;
    inv[col] = 1.0f / sqrtf(var + 1e-5f);
}

// ---------------- BN apply + ReLU (in place) ----------------
__global__ void bn_apply_kernel(float* __restrict__ X, int n, int cols,
                                const float* __restrict__ mean, const float* __restrict__ inv,
                                const float* __restrict__ g, const float* __restrict__ be)
{
    int idx = blockIdx.x * blockDim.x + threadIdx.x;
    if (idx < n) {
        int col = idx & (cols - 1);
        float v = (X[idx] - mean[col]) * inv[col] * g[col] + be[col];
        X[idx] = fmaxf(v, 0.f);
    }
}

// ---------------- final matvec ----------------
__global__ void gemm5_kernel(const float* __restrict__ U4, const float* __restrict__ W5,
                             const float* __restrict__ b5, float* __restrict__ out)
{
    int warp = (blockIdx.x * blockDim.x + threadIdx.x) >> 5;
    int lane = threadIdx.x & 31;
    if (warp >= 8192) return;
    float s = U4[(size_t)warp * 64 + lane] * W5[lane]
            + U4[(size_t)warp * 64 + 32 + lane] * W5[32 + lane];
#pragma unroll
    for (int o = 16; o; o >>= 1) s += __shfl_xor_sync(0xffffffffu, s, o);
    if (lane == 0) out[warp] = s + b5[0];
}

// ---------------- launcher ----------------
extern "C" void kernel_launch(void* const* d_in, const int* in_sizes, int n_in,
                              void* d_out, int out_size)
{
    const float* lufeat = (const float*)d_in[0];
    const int*   llabel = (const int*)  d_in[1];
    const float* W1 = (const float*)d_in[2];
    const float* b1 = (const float*)d_in[3];
    const float* W2 = (const float*)d_in[4];
    const float* b2 = (const float*)d_in[5];
    const float* W3 = (const float*)d_in[6];
    const float* b3 = (const float*)d_in[7];
    const float* W4 = (const float*)d_in[8];
    const float* b4 = (const float*)d_in[9];
    const float* W5 = (const float*)d_in[10];
    const float* b5 = (const float*)d_in[11];
    const float* g1 = (const float*)d_in[12];
    const float* be1 = (const float*)d_in[13];
    const float* g2 = (const float*)d_in[14];
    const float* be2 = (const float*)d_in[15];
    const float* mbank0 = (const float*)d_in[16];
    const float* start0 = (const float*)d_in[17];
    float* out = (float*)d_out;

    float *H, *MB, *UF, *Y3, *Y4, *PS, *PQ, *MEAN, *INV, *W12P, *B12;
    int *OCC, *CNT;
    __nv_bfloat16 *W2h, *W2l, *W3h, *W3l, *W4h, *W4l, *W12h, *W12l;
    cudaGetSymbolAddress((void**)&H,  g_H);
    cudaGetSymbolAddress((void**)&MB, g_MB);
    cudaGetSymbolAddress((void**)&UF, g_UF);
    cudaGetSymbolAddress((void**)&Y3, g_Y3);
    cudaGetSymbolAddress((void**)&Y4, g_Y4);
    cudaGetSymbolAddress((void**)&PS, g_PS);
    cudaGetSymbolAddress((void**)&PQ, g_PQ);
    cudaGetSymbolAddress((void**)&MEAN, g_MEAN);
    cudaGetSymbolAddress((void**)&INV,  g_INV);
    cudaGetSymbolAddress((void**)&OCC, g_OCC);
    cudaGetSymbolAddress((void**)&CNT, g_CNT);
    cudaGetSymbolAddress((void**)&W12P, g_W12P);
    cudaGetSymbolAddress((void**)&B12, g_B12);
    cudaGetSymbolAddress((void**)&W2h, g_W2h); cudaGetSymbolAddress((void**)&W2l, g_W2l);
    cudaGetSymbolAddress((void**)&W3h, g_W3h); cudaGetSymbolAddress((void**)&W3l, g_W3l);
    cudaGetSymbolAddress((void**)&W4h, g_W4h); cudaGetSymbolAddress((void**)&W4l, g_W4l);
    cudaGetSymbolAddress((void**)&W12h, g_W12h); cudaGetSymbolAddress((void**)&W12l, g_W12l);

    const int SMEM_BYTES = 81920;
    const int SMEM_N64 = 61440;
    cudaFuncSetAttribute(mma_gemm, cudaFuncAttributeMaxDynamicSharedMemorySize, SMEM_BYTES);
    cudaFuncSetAttribute(mma_gemm_sk, cudaFuncAttributeMaxDynamicSharedMemorySize, SMEM_BYTES);
    cudaFuncSetAttribute(mma_gemm_n64, cudaFuncAttributeMaxDynamicSharedMemorySize, SMEM_N64);

    // weight splits (transposed) for W2/W3/W4; label compaction
    split_all_kernel<<<960, 256>>>(W2, W3, W4, W2h, W2l, W3h, W3l, W4h, W4l);
    rank_kernel<<<40, 32>>>(llabel, OCC, CNT);
    bias12_kernel<<<1, 256>>>(b1, W2, b2, B12);

    // W12 = W1 @ W2 via split-K x4 (64 CTAs), then fused reduce+split+transpose
    mma_gemm_sk<<<dim3(2, 8, 4), 256, SMEM_BYTES>>>(W1, 512, W2h, W2l, W12P, 1024, 256, 512, 128);
    w12_reduce_split<<<1024, 256>>>(W12P, W12h, W12l);

    // h = lufeat @ W12 + b12 ; normalize rows
    mma_gemm<<<dim3(2, 128), 256, SMEM_BYTES>>>(lufeat, 1024, W12h, W12l, B12, H, 256, 1024);
    norm_rows_kernel<<<2048, 256>>>(H);

    // memory bank EMA
    ema_kernel<<<40, 256>>>(H, OCC, CNT, mbank0, start0, MB, out + 16384);

    // distances
    dist_kernel<<<256, 256>>>(H, MB, out, UF);

    // layer 3: UF(8192x296, stride 320, zero-padded) @ W3 (Kp=320)
    mma_gemm<<<dim3(2, 64), 256, SMEM_BYTES>>>(UF, 320, W3h, W3l, b3, Y3, 256, 320);
    bn_part_kernel<<<64, 256>>>(Y3, 256, PS, PQ);
    bn_stats_kernel<<<1, 256>>>(PS, PQ, 256, MEAN, INV);
    bn_apply_kernel<<<(8192 * 256 + 255) / 256, 256>>>(Y3, 8192 * 256, 256, MEAN, INV, g1, be1);

    // layer 4: Y3(8192x256) @ W4 (N=64, BN=64 variant, Kp=256)
    mma_gemm_n64<<<dim3(1, 64), 256, SMEM_N64>>>(Y3, 256, W4h, W4l, b4, Y4, 64, 256);
    bn_part_kernel<<<64, 64>>>(Y4, 64, PS, PQ);
    bn_stats_kernel<<<1, 64>>>(PS, PQ, 64, MEAN, INV);
    bn_apply_kernel<<<(8192 * 64 + 255) / 256, 256>>>(Y4, 8192 * 64, 64, MEAN, INV, g2, be2);

    // uscores
    gemm5_kernel<<<1024, 256>>>(Y4, W5, b5, out + 8192);
}